// round 9
// baseline (speedup 1.0000x reference)
#include <cuda_runtime.h>
#include <cuda_bf16.h>
#include <math.h>
#include <stdint.h>

typedef __nv_bfloat16 bf16;

// Problem constants
#define MM 1024
#define NN 4096
#define DD 128
#define HH 32
#define PP 4096
#define KVLEN 5120   // PP + MM
#define MN (MM * NN)

// ---------------------------------------------------------------------------
// Scratch (allocation-free rule: __device__ globals)
// ---------------------------------------------------------------------------
__device__ float g_qkv[3ull * MN];                   // q | k | v (k unused now)
__device__ bf16 g_Xhi[MN];
__device__ bf16 g_Xlo[MN];
__device__ bf16 g_Wthi[3ull * NN * NN];              // W transposed [n][k], hi
__device__ bf16 g_Wtlo[3ull * NN * NN];
__device__ bf16 g_Qhi[MN];
__device__ bf16 g_Qlo[MN];
__device__ bf16 g_Khi[(size_t)HH * KVLEN * DD];      // [h][kv][d]
__device__ bf16 g_Klo[(size_t)HH * KVLEN * DD];
__device__ bf16 g_Vthi[(size_t)HH * DD * KVLEN];     // [h][d][kv]
__device__ bf16 g_Vtlo[(size_t)HH * DD * KVLEN];

// ---------------------------------------------------------------------------
// Helpers
// ---------------------------------------------------------------------------
__device__ __forceinline__ uint32_t smem_u32(const void* p) {
    uint32_t a;
    asm("{ .reg .u64 t; cvta.to.shared.u64 t, %1; cvt.u32.u64 %0, t; }" : "=r"(a) : "l"(p));
    return a;
}
__device__ __forceinline__ void ldsm_x4(uint32_t* r, uint32_t addr) {
    asm volatile("ldmatrix.sync.aligned.m8n8.x4.shared.b16 {%0,%1,%2,%3}, [%4];"
                 : "=r"(r[0]), "=r"(r[1]), "=r"(r[2]), "=r"(r[3]) : "r"(addr));
}
__device__ __forceinline__ void cp16(uint32_t saddr, const void* gaddr) {
    asm volatile("cp.async.cg.shared.global [%0], [%1], 16;"
                 :: "r"(saddr), "l"(gaddr) : "memory");
}
#define CP_COMMIT() asm volatile("cp.async.commit_group;" ::: "memory")
#define CP_WAIT1() asm volatile("cp.async.wait_group 1;" ::: "memory")
#define CP_WAIT0() asm volatile("cp.async.wait_group 0;" ::: "memory")

#define MMA16816(d, a, b)                                              \
    asm volatile(                                                      \
        "mma.sync.aligned.m16n8k16.row.col.f32.bf16.bf16.f32 "         \
        "{%0,%1,%2,%3}, {%4,%5,%6,%7}, {%8,%9}, {%0,%1,%2,%3};"        \
        : "+f"((d)[0]), "+f"((d)[1]), "+f"((d)[2]), "+f"((d)[3])       \
        : "r"((a)[0]), "r"((a)[1]), "r"((a)[2]), "r"((a)[3]),          \
          "r"((b)[0]), "r"((b)[1]))

__device__ __forceinline__ void split2(float x, bf16& h, bf16& l) {
    h = __float2bfloat16(x);
    l = __float2bfloat16(x - __bfloat162float(h));
}
__device__ __forceinline__ uint32_t packsplit_hi(float a, float b) {
    __nv_bfloat162 t(__float2bfloat16(a), __float2bfloat16(b));
    return *(uint32_t*)&t;
}
__device__ __forceinline__ uint32_t packsplit_lo(float a, float b) {
    bf16 ha = __float2bfloat16(a), hb = __float2bfloat16(b);
    __nv_bfloat162 t(__float2bfloat16(a - __bfloat162float(ha)),
                     __float2bfloat16(b - __bfloat162float(hb)));
    return *(uint32_t*)&t;
}

// ---------------------------------------------------------------------------
// RMSNorm over rows of X [1024, 4096], fused bf16 hi/lo split output
// ---------------------------------------------------------------------------
__global__ __launch_bounds__(256) void rmsnorm_split_x(const float* __restrict__ X,
                                                       bf16* __restrict__ hi,
                                                       bf16* __restrict__ lo) {
    int row = blockIdx.x;
    const float4* x4 = (const float4*)(X + (size_t)row * NN);
    float4 v[4];
    float ss = 0.f;
#pragma unroll
    for (int i = 0; i < 4; i++) {
        v[i] = x4[threadIdx.x + i * 256];
        ss += v[i].x * v[i].x + v[i].y * v[i].y + v[i].z * v[i].z + v[i].w * v[i].w;
    }
#pragma unroll
    for (int o = 16; o; o >>= 1) ss += __shfl_xor_sync(0xffffffffu, ss, o);
    __shared__ float wsum[8];
    int warp = threadIdx.x >> 5, lane = threadIdx.x & 31;
    if (lane == 0) wsum[warp] = ss;
    __syncthreads();
    float tot = 0.f;
#pragma unroll
    for (int w = 0; w < 8; w++) tot += wsum[w];
    float s = rsqrtf(tot * (1.0f / (float)NN));
#pragma unroll
    for (int i = 0; i < 4; i++) {
        float a = v[i].x * s, b = v[i].y * s, c = v[i].z * s, d = v[i].w * s;
        size_t off = (size_t)row * NN + (threadIdx.x + i * 256) * 4;
        bf16 h0, h1, h2, h3, l0, l1, l2, l3;
        split2(a, h0, l0); split2(b, h1, l1);
        split2(c, h2, l2); split2(d, h3, l3);
        *(__nv_bfloat162*)(hi + off)     = __nv_bfloat162(h0, h1);
        *(__nv_bfloat162*)(hi + off + 2) = __nv_bfloat162(h2, h3);
        *(__nv_bfloat162*)(lo + off)     = __nv_bfloat162(l0, l1);
        *(__nv_bfloat162*)(lo + off + 2) = __nv_bfloat162(l2, l3);
    }
}

// ---------------------------------------------------------------------------
// Transpose + split W [K, N] fp32 -> Wt hi/lo bf16 [N, K]
// ---------------------------------------------------------------------------
__global__ __launch_bounds__(256) void wsplit_kernel(const float* __restrict__ W,
                                                     bf16* __restrict__ hi,
                                                     bf16* __restrict__ lo) {
    __shared__ float t[32][33];
    int tx = threadIdx.x & 31, ty = threadIdx.x >> 5;
    int n0 = blockIdx.x * 32, k0 = blockIdx.y * 32;
#pragma unroll
    for (int i = 0; i < 4; i++)
        t[ty + i * 8][tx] = W[(size_t)(k0 + ty + i * 8) * NN + n0 + tx];
    __syncthreads();
#pragma unroll
    for (int i = 0; i < 4; i++) {
        float v = t[tx][ty + i * 8];
        bf16 h, l;
        split2(v, h, l);
        size_t off = (size_t)(n0 + ty + i * 8) * NN + k0 + tx;
        hi[off] = h;
        lo[off] = l;
    }
}

// ---------------------------------------------------------------------------
// Per-head RMSNorm over D=128.
// q rows: norm + split -> Qh/Ql (layout [m][h*D+d]).
// k rows: norm + split -> DIRECTLY into KV cache appended region
//         Kh/Kl[h][PP+m][d]  (no fp32 writeback).
// ---------------------------------------------------------------------------
__global__ __launch_bounds__(256) void qknorm_split_kernel(const float* __restrict__ q,
                                                           const float* __restrict__ k,
                                                           bf16* __restrict__ Qh,
                                                           bf16* __restrict__ Ql,
                                                           bf16* __restrict__ Kh,
                                                           bf16* __restrict__ Kl) {
    int gw = (int)((blockIdx.x * blockDim.x + threadIdx.x) >> 5);
    int lane = threadIdx.x & 31;
    bool isq = (gw < MM * HH);
    int row = isq ? gw : gw - MM * HH;
    const float* src = isq ? q : k;
    float4 a = ((const float4*)(src + (size_t)row * DD))[lane];
    float ss = a.x * a.x + a.y * a.y + a.z * a.z + a.w * a.w;
#pragma unroll
    for (int o = 16; o; o >>= 1) ss += __shfl_xor_sync(0xffffffffu, ss, o);
    float s = rsqrtf(ss * (1.0f / (float)DD));
    a.x *= s; a.y *= s; a.z *= s; a.w *= s;
    bf16 h0, h1, h2, h3, l0, l1, l2, l3;
    split2(a.x, h0, l0); split2(a.y, h1, l1);
    split2(a.z, h2, l2); split2(a.w, h3, l3);
    size_t off;
    bf16 *dh, *dl;
    if (isq) {
        off = (size_t)row * DD + lane * 4;
        dh = Qh; dl = Ql;
    } else {
        int m = row / HH, h = row % HH;
        off = ((size_t)h * KVLEN + PP + m) * DD + lane * 4;
        dh = Kh; dl = Kl;
    }
    *(__nv_bfloat162*)(dh + off)     = __nv_bfloat162(h0, h1);
    *(__nv_bfloat162*)(dh + off + 2) = __nv_bfloat162(h2, h3);
    *(__nv_bfloat162*)(dl + off)     = __nv_bfloat162(l0, l1);
    *(__nv_bfloat162*)(dl + off + 2) = __nv_bfloat162(l2, l3);
}

// ---------------------------------------------------------------------------
// Build K cache hi/lo: CACHE portion only ([h][0..PP][d])
// ---------------------------------------------------------------------------
__global__ __launch_bounds__(256) void build_khl(const float* __restrict__ cacheK,
                                                 bf16* __restrict__ Kh,
                                                 bf16* __restrict__ Kl) {
    size_t e = ((size_t)blockIdx.x * 256 + threadIdx.x) * 4;   // over HH*PP*DD
    int h = (int)(e / ((size_t)PP * DD));
    int rem = (int)(e % ((size_t)PP * DD));
    float4 v = *(const float4*)(cacheK + e);
    bf16 h0, h1, h2, h3, l0, l1, l2, l3;
    split2(v.x, h0, l0); split2(v.y, h1, l1);
    split2(v.z, h2, l2); split2(v.w, h3, l3);
    size_t o = (size_t)h * KVLEN * DD + rem;
    *(__nv_bfloat162*)(Kh + o)     = __nv_bfloat162(h0, h1);
    *(__nv_bfloat162*)(Kh + o + 2) = __nv_bfloat162(h2, h3);
    *(__nv_bfloat162*)(Kl + o)     = __nv_bfloat162(l0, l1);
    *(__nv_bfloat162*)(Kl + o + 2) = __nv_bfloat162(l2, l3);
}

// ---------------------------------------------------------------------------
// Build V^T hi/lo: [h][d][kv]
// ---------------------------------------------------------------------------
__global__ __launch_bounds__(256) void build_vt(const float* __restrict__ cacheV,
                                                const float* __restrict__ vproj,
                                                bf16* __restrict__ Vh,
                                                bf16* __restrict__ Vl) {
    __shared__ float t[32][33];
    int tx = threadIdx.x & 31, ty = threadIdx.x >> 5;
    int kv0 = blockIdx.x * 32, d0 = blockIdx.y * 32, h = blockIdx.z;
#pragma unroll
    for (int i = 0; i < 4; i++) {
        int r = kv0 + ty + i * 8;
        int c = d0 + tx;
        float v = (r < PP)
            ? cacheV[((size_t)h * PP + r) * DD + c]
            : vproj[(size_t)(r - PP) * NN + h * DD + c];
        t[ty + i * 8][tx] = v;
    }
    __syncthreads();
#pragma unroll
    for (int i = 0; i < 4; i++) {
        int d = d0 + ty + i * 8;
        float v = t[tx][ty + i * 8];
        bf16 hh, ll;
        split2(v, hh, ll);
        size_t off = ((size_t)h * DD + d) * KVLEN + kv0 + tx;
        Vh[off] = hh;
        Vl[off] = ll;
    }
}

// ---------------------------------------------------------------------------
// bf16x3 GEMM (mma.sync m16n8k16), 3-slot / 2-in-flight cp.async pipeline,
// one __syncthreads per K-chunk. B fragments via ldsm_x4 (2 j-tiles/instr).
// ---------------------------------------------------------------------------
template <int BN, int WN>
__global__ __launch_bounds__(256, 1) void gemm3(
    const bf16* __restrict__ Ah, const bf16* __restrict__ Al,
    const bf16* __restrict__ Bh, const bf16* __restrict__ Bl,
    float* __restrict__ C, int K, int lda, int ldb, int ldc) {
    constexpr int BM = 128;
    constexpr int NFR = WN / 8;          // 8
    constexpr int NP = NFR / 2;          // 4 pairs
    constexpr int PADB = 80;
    constexpr int STG = (2 * BM + 2 * BN) * PADB;
    extern __shared__ char smraw[];

    const int tid = threadIdx.x;
    const int lane = tid & 31, wid = tid >> 5;
    const int wr = wid >> 2, wc = wid & 3;
    const int m0 = blockIdx.y * BM, n0 = blockIdx.x * BN;

    float acc[4][NFR][4];
#pragma unroll
    for (int f = 0; f < 4; f++)
#pragma unroll
        for (int j = 0; j < NFR; j++)
#pragma unroll
            for (int x = 0; x < 4; x++) acc[f][j][x] = 0.f;

    const uint32_t sbase = smem_u32(smraw);
    const uint32_t aoff = (uint32_t)((wr * 64 + (lane & 15)) * PADB + (lane >> 4) * 16);
    // ldsm_x4 B mapping: lane groups (0-7,8-15,16-23,24-31) ->
    // (j+0,k0), (j+0,k1), (j+1,k0), (j+1,k1)
    const uint32_t boff4 = (uint32_t)((wc * WN + ((lane >> 4) & 1) * 8 + (lane & 7)) * PADB
                                      + ((lane >> 3) & 1) * 16);

    auto issue = [&](int slot, int k0) {
        uint32_t ba = sbase + slot * STG;
        const bf16* pAh = Ah + (size_t)m0 * lda + k0;
        const bf16* pAl = Al + (size_t)m0 * lda + k0;
#pragma unroll
        for (int i = tid; i < BM * 4; i += 256) {
            int r = i >> 2, cb = (i & 3) * 16;
            cp16(ba + r * PADB + cb, (const char*)(pAh + (size_t)r * lda) + cb);
            cp16(ba + BM * PADB + r * PADB + cb, (const char*)(pAl + (size_t)r * lda) + cb);
        }
        uint32_t bb = ba + 2 * BM * PADB;
        const bf16* pBh = Bh + (size_t)n0 * ldb + k0;
        const bf16* pBl = Bl + (size_t)n0 * ldb + k0;
#pragma unroll
        for (int i = tid; i < BN * 4; i += 256) {
            int r = i >> 2, cb = (i & 3) * 16;
            cp16(bb + r * PADB + cb, (const char*)(pBh + (size_t)r * ldb) + cb);
            cp16(bb + BN * PADB + r * PADB + cb, (const char*)(pBl + (size_t)r * ldb) + cb);
        }
        CP_COMMIT();
    };

    const int nch = K >> 5;
    issue(0, 0);
    if (nch > 1) issue(1, 32);

    for (int kc = 0; kc < nch; kc++) {
        if (kc + 1 < nch) { CP_WAIT1(); } else { CP_WAIT0(); }
        __syncthreads();
        if (kc + 2 < nch) issue((kc + 2) % 3, (kc + 2) << 5);

        const uint32_t aH = sbase + (kc % 3) * STG;
        const uint32_t aL = aH + BM * PADB;
        const uint32_t bH = aL + BM * PADB;
        const uint32_t bL = bH + BN * PADB;
#pragma unroll
        for (int ks = 0; ks < 2; ks++) {
            uint32_t ah[4][4], al[4][4];
#pragma unroll
            for (int f = 0; f < 4; f++) {
                uint32_t off = aoff + f * 16 * PADB + ks * 32;
                ldsm_x4(ah[f], aH + off);
                ldsm_x4(al[f], aL + off);
            }
            uint32_t b4h[NP][4], b4l[NP][4];
#pragma unroll
            for (int p = 0; p < NP; p++) {
                uint32_t off = boff4 + p * 16 * PADB + ks * 32;
                ldsm_x4(b4h[p], bH + off);
                ldsm_x4(b4l[p], bL + off);
            }
#pragma unroll
            for (int j = 0; j < NFR; j++) {
                uint32_t* bh = &b4h[j >> 1][(j & 1) * 2];
                uint32_t* bl = &b4l[j >> 1][(j & 1) * 2];
#pragma unroll
                for (int f = 0; f < 4; f++) MMA16816(acc[f][j], ah[f], bh);
#pragma unroll
                for (int f = 0; f < 4; f++) MMA16816(acc[f][j], ah[f], bl);
#pragma unroll
                for (int f = 0; f < 4; f++) MMA16816(acc[f][j], al[f], bh);
            }
        }
    }
    __syncthreads();

#pragma unroll
    for (int f = 0; f < 4; f++) {
        int row = m0 + wr * 64 + f * 16 + (lane >> 2);
#pragma unroll
        for (int j = 0; j < NFR; j++) {
            int col = n0 + wc * WN + j * 8 + (lane & 3) * 2;
            *(float2*)(C + (size_t)row * ldc + col) = make_float2(acc[f][j][0], acc[f][j][1]);
            *(float2*)(C + (size_t)(row + 8) * ldc + col) = make_float2(acc[f][j][2], acc[f][j][3]);
        }
    }
}

// ---------------------------------------------------------------------------
// Fused flash attention on mma.sync, bf16x3, ldsm_x4 fragment loads.
// Block: 128 q-rows x 1 head. 8 warps x 16 rows. KV chunks of 64, 2 stages.
// ---------------------------------------------------------------------------
#define FA_KPAD 272
#define FA_VPAD 144
#define FA_QB (128 * FA_KPAD)
#define FA_KT (64 * FA_KPAD)
#define FA_VT (128 * FA_VPAD)
#define FA_STG (2 * FA_KT + 2 * FA_VT)
#define FA_SMEM (2 * FA_QB + 2 * FA_STG)   // 212992

__global__ __launch_bounds__(256, 1) void attn_fused(
    const bf16* __restrict__ Qh_, const bf16* __restrict__ Ql_,
    const bf16* __restrict__ Kh_, const bf16* __restrict__ Kl_,
    const bf16* __restrict__ Vh_, const bf16* __restrict__ Vl_,
    float* __restrict__ out) {
    extern __shared__ char sm[];
    const int tid = threadIdx.x, lane = tid & 31, wid = tid >> 5;
    const int m0 = blockIdx.x * 128, h = blockIdx.y;
    const uint32_t sb = smem_u32(sm);

    const bf16* Khh = Kh_ + (size_t)h * KVLEN * DD;
    const bf16* Klh = Kl_ + (size_t)h * KVLEN * DD;
    const bf16* Vhh = Vh_ + (size_t)h * DD * KVLEN;
    const bf16* Vlh = Vl_ + (size_t)h * DD * KVLEN;

    // Q tile via cp.async (group 0)
#pragma unroll
    for (int i = tid; i < 128 * 16; i += 256) {
        int r = i >> 4, c = i & 15;
        size_t go = (size_t)(m0 + r) * NN + h * DD + c * 8;
        cp16(sb + r * FA_KPAD + c * 16, Qh_ + go);
        cp16(sb + FA_QB + r * FA_KPAD + c * 16, Ql_ + go);
    }
    CP_COMMIT();

    auto issue = [&](int s, int kv0) {
        uint32_t kb = sb + 2 * FA_QB + s * FA_STG;
#pragma unroll
        for (int i = tid; i < 1024; i += 256) {
            int r = i >> 4, c = i & 15;
            size_t go = (size_t)(kv0 + r) * DD + c * 8;
            cp16(kb + r * FA_KPAD + c * 16, Khh + go);
            cp16(kb + FA_KT + r * FA_KPAD + c * 16, Klh + go);
        }
        uint32_t vb = kb + 2 * FA_KT;
#pragma unroll
        for (int i = tid; i < 1024; i += 256) {
            int r = i >> 3, c = i & 7;
            size_t go = (size_t)r * KVLEN + kv0 + c * 8;
            cp16(vb + r * FA_VPAD + c * 16, Vhh + go);
            cp16(vb + FA_VT + r * FA_VPAD + c * 16, Vlh + go);
        }
        CP_COMMIT();
    };

    float oacc[16][4];
#pragma unroll
    for (int j = 0; j < 16; j++)
#pragma unroll
        for (int x = 0; x < 4; x++) oacc[j][x] = 0.f;
    float mrow0 = -INFINITY, mrow8 = -INFINITY;
    float lrow0 = 0.f, lrow8 = 0.f;

    const uint32_t qoff = (uint32_t)((wid * 16 + (lane & 15)) * FA_KPAD + (lane >> 4) * 16);
    const uint32_t koff4 = (uint32_t)((((lane >> 4) & 1) * 8 + (lane & 7)) * FA_KPAD
                                      + ((lane >> 3) & 1) * 16);
    const uint32_t voff4 = (uint32_t)((((lane >> 4) & 1) * 8 + (lane & 7)) * FA_VPAD
                                      + ((lane >> 3) & 1) * 16);

    issue(0, 0);

    for (int ch = 0; ch < KVLEN / 64; ch++) {
        const int s = ch & 1;
        if (ch + 1 < KVLEN / 64) {
            issue(s ^ 1, (ch + 1) * 64);
            CP_WAIT1();
        } else {
            CP_WAIT0();
        }
        __syncthreads();

        const uint32_t bKh = sb + 2 * FA_QB + s * FA_STG;
        const uint32_t bKl = bKh + FA_KT;
        const uint32_t bVh = bKh + 2 * FA_KT;
        const uint32_t bVl = bVh + FA_VT;

        // S = Q @ K^T
        float sacc[8][4];
#pragma unroll
        for (int j = 0; j < 8; j++)
#pragma unroll
            for (int x = 0; x < 4; x++) sacc[j][x] = 0.f;
#pragma unroll
        for (int ks = 0; ks < 8; ks++) {
            uint32_t qh[4], ql[4];
            ldsm_x4(qh, sb + qoff + ks * 32);
            ldsm_x4(ql, sb + FA_QB + qoff + ks * 32);
            uint32_t k4h[4][4], k4l[4][4];
#pragma unroll
            for (int p = 0; p < 4; p++) {
                uint32_t off = koff4 + p * 16 * FA_KPAD + ks * 32;
                ldsm_x4(k4h[p], bKh + off);
                ldsm_x4(k4l[p], bKl + off);
            }
#pragma unroll
            for (int j = 0; j < 8; j++) MMA16816(sacc[j], qh, (&k4h[j >> 1][(j & 1) * 2]));
#pragma unroll
            for (int j = 0; j < 8; j++) MMA16816(sacc[j], qh, (&k4l[j >> 1][(j & 1) * 2]));
#pragma unroll
            for (int j = 0; j < 8; j++) MMA16816(sacc[j], ql, (&k4h[j >> 1][(j & 1) * 2]));
        }

        // Online softmax
        float mx0 = -INFINITY, mx8 = -INFINITY;
#pragma unroll
        for (int j = 0; j < 8; j++) {
            mx0 = fmaxf(mx0, fmaxf(sacc[j][0], sacc[j][1]));
            mx8 = fmaxf(mx8, fmaxf(sacc[j][2], sacc[j][3]));
        }
        mx0 = fmaxf(mx0, __shfl_xor_sync(0xffffffffu, mx0, 1));
        mx0 = fmaxf(mx0, __shfl_xor_sync(0xffffffffu, mx0, 2));
        mx8 = fmaxf(mx8, __shfl_xor_sync(0xffffffffu, mx8, 1));
        mx8 = fmaxf(mx8, __shfl_xor_sync(0xffffffffu, mx8, 2));
        float mn0 = fmaxf(mrow0, mx0), mn8 = fmaxf(mrow8, mx8);
        float sc0 = __expf(mrow0 - mn0), sc8 = __expf(mrow8 - mn8);
        mrow0 = mn0; mrow8 = mn8;
        float ps0 = 0.f, ps8 = 0.f;
#pragma unroll
        for (int j = 0; j < 8; j++) {
            sacc[j][0] = __expf(sacc[j][0] - mn0);
            sacc[j][1] = __expf(sacc[j][1] - mn0);
            sacc[j][2] = __expf(sacc[j][2] - mn8);
            sacc[j][3] = __expf(sacc[j][3] - mn8);
            ps0 += sacc[j][0] + sacc[j][1];
            ps8 += sacc[j][2] + sacc[j][3];
        }
        lrow0 = lrow0 * sc0 + ps0;
        lrow8 = lrow8 * sc8 + ps8;
#pragma unroll
        for (int j = 0; j < 16; j++) {
            oacc[j][0] *= sc0; oacc[j][1] *= sc0;
            oacc[j][2] *= sc8; oacc[j][3] *= sc8;
        }

        // P fragments: hi/lo split in regs
        uint32_t ph[4][4], pl[4][4];
#pragma unroll
        for (int kk = 0; kk < 4; kk++) {
            ph[kk][0] = packsplit_hi(sacc[2 * kk][0], sacc[2 * kk][1]);
            ph[kk][1] = packsplit_hi(sacc[2 * kk][2], sacc[2 * kk][3]);
            ph[kk][2] = packsplit_hi(sacc[2 * kk + 1][0], sacc[2 * kk + 1][1]);
            ph[kk][3] = packsplit_hi(sacc[2 * kk + 1][2], sacc[2 * kk + 1][3]);
            pl[kk][0] = packsplit_lo(sacc[2 * kk][0], sacc[2 * kk][1]);
            pl[kk][1] = packsplit_lo(sacc[2 * kk][2], sacc[2 * kk][3]);
            pl[kk][2] = packsplit_lo(sacc[2 * kk + 1][0], sacc[2 * kk + 1][1]);
            pl[kk][3] = packsplit_lo(sacc[2 * kk + 1][2], sacc[2 * kk + 1][3]);
        }

        // O += P @ V^T, halves of 8 j-tiles (pairs via ldsm_x4)
#pragma unroll
        for (int kk = 0; kk < 4; kk++) {
#pragma unroll
            for (int jh = 0; jh < 2; jh++) {
                uint32_t v4h[4][4], v4l[4][4];
#pragma unroll
                for (int p = 0; p < 4; p++) {
                    uint32_t off = voff4 + (jh * 64 + p * 16) * FA_VPAD + kk * 32;
                    ldsm_x4(v4h[p], bVh + off);
                    ldsm_x4(v4l[p], bVl + off);
                }
#pragma unroll
                for (int j = 0; j < 8; j++)
                    MMA16816(oacc[jh * 8 + j], ph[kk], (&v4h[j >> 1][(j & 1) * 2]));
#pragma unroll
                for (int j = 0; j < 8; j++)
                    MMA16816(oacc[jh * 8 + j], ph[kk], (&v4l[j >> 1][(j & 1) * 2]));
#pragma unroll
                for (int j = 0; j < 8; j++)
                    MMA16816(oacc[jh * 8 + j], pl[kk], (&v4h[j >> 1][(j & 1) * 2]));
            }
        }
        __syncthreads();
    }

    lrow0 += __shfl_xor_sync(0xffffffffu, lrow0, 1);
    lrow0 += __shfl_xor_sync(0xffffffffu, lrow0, 2);
    lrow8 += __shfl_xor_sync(0xffffffffu, lrow8, 1);
    lrow8 += __shfl_xor_sync(0xffffffffu, lrow8, 2);
    float inv0 = 1.0f / lrow0, inv8 = 1.0f / lrow8;
    int r0 = m0 + wid * 16 + (lane >> 2);
#pragma unroll
    for (int j = 0; j < 16; j++) {
        int col = h * DD + j * 8 + (lane & 3) * 2;
        *(float2*)(out + (size_t)r0 * NN + col) =
            make_float2(oacc[j][0] * inv0, oacc[j][1] * inv0);
        *(float2*)(out + (size_t)(r0 + 8) * NN + col) =
            make_float2(oacc[j][2] * inv8, oacc[j][3] * inv8);
    }
}

// ---------------------------------------------------------------------------
extern "C" void kernel_launch(void* const* d_in, const int* in_sizes, int n_in,
                              void* d_out, int out_size) {
    const float* X  = (const float*)d_in[0];
    const float* Wq = (const float*)d_in[1];
    const float* Wk = (const float*)d_in[2];
    const float* Wv = (const float*)d_in[3];
    const float* cK = (const float*)d_in[4];
    const float* cV = (const float*)d_in[5];
    float* out = (float*)d_out;

    float* qkv;
    bf16 *Xhi, *Xlo, *Wthi, *Wtlo, *Qhi, *Qlo, *Khi, *Klo, *Vthi, *Vtlo;
    cudaGetSymbolAddress((void**)&qkv, g_qkv);
    cudaGetSymbolAddress((void**)&Xhi, g_Xhi);
    cudaGetSymbolAddress((void**)&Xlo, g_Xlo);
    cudaGetSymbolAddress((void**)&Wthi, g_Wthi);
    cudaGetSymbolAddress((void**)&Wtlo, g_Wtlo);
    cudaGetSymbolAddress((void**)&Qhi, g_Qhi);
    cudaGetSymbolAddress((void**)&Qlo, g_Qlo);
    cudaGetSymbolAddress((void**)&Khi, g_Khi);
    cudaGetSymbolAddress((void**)&Klo, g_Klo);
    cudaGetSymbolAddress((void**)&Vthi, g_Vthi);
    cudaGetSymbolAddress((void**)&Vtlo, g_Vtlo);

    float* q = qkv;
    float* k = qkv + (size_t)MN;
    float* v = qkv + 2ull * MN;

    const int SM256 = 3 * (2 * 128 + 2 * 256) * 80;   // 184320 (3 slots)
    cudaFuncSetAttribute(gemm3<256, 64>, cudaFuncAttributeMaxDynamicSharedMemorySize, SM256);
    cudaFuncSetAttribute(attn_fused, cudaFuncAttributeMaxDynamicSharedMemorySize, FA_SMEM);

    // 1) RMSNorm X + split (fused)                                  [launch 1]
    rmsnorm_split_x<<<MM, 256>>>(X, Xhi, Xlo);

    // 2) W transpose+split                                          [2..4]
    dim3 wgrid(NN / 32, NN / 32);
    wsplit_kernel<<<wgrid, 256>>>(Wq, Wthi + 0ull * NN * NN, Wtlo + 0ull * NN * NN);
    wsplit_kernel<<<wgrid, 256>>>(Wk, Wthi + 1ull * NN * NN, Wtlo + 1ull * NN * NN);
    wsplit_kernel<<<wgrid, 256>>>(Wv, Wthi + 2ull * NN * NN, Wtlo + 2ull * NN * NN);

    // 3) QKV = Xn @ W — per-z launches (launch 6 = gemm3(k) for ncu) [5..7]
    dim3 ggrid(NN / 256, MM / 128);
    gemm3<256, 64><<<ggrid, 256, SM256>>>(Xhi, Xlo, Wthi + 0ull * NN * NN,
                                          Wtlo + 0ull * NN * NN, q, NN, NN, NN, NN);
    gemm3<256, 64><<<ggrid, 256, SM256>>>(Xhi, Xlo, Wthi + 1ull * NN * NN,
                                          Wtlo + 1ull * NN * NN, k, NN, NN, NN, NN);
    gemm3<256, 64><<<ggrid, 256, SM256>>>(Xhi, Xlo, Wthi + 2ull * NN * NN,
                                          Wtlo + 2ull * NN * NN, v, NN, NN, NN, NN);

    // 4) qk-norm: q -> Qhi/Qlo; k -> Khi/Klo appended region          [8]
    qknorm_split_kernel<<<(2 * MM * HH * 32) / 256, 256>>>(q, k, Qhi, Qlo, Khi, Klo);

    // 5) KV cache conversions (cache portion of K; all of V^T)       [9,10]
    build_khl<<<(int)((size_t)HH * PP * DD / 1024), 256>>>(cK, Khi, Klo);
    build_vt<<<dim3(KVLEN / 32, DD / 32, HH), 256>>>(cV, v, Vthi, Vtlo);

    // 6) fused flash attention -> d_out                              [11]
    attn_fused<<<dim3(MM / 128, HH), 256, FA_SMEM>>>(
        Qhi, Qlo, Khi, Klo, Vthi, Vtlo, out);
}

// round 10
// speedup vs baseline: 1.0304x; 1.0304x over previous
#include <cuda_runtime.h>
#include <cuda_bf16.h>
#include <math.h>
#include <stdint.h>

typedef __nv_bfloat16 bf16;

// Problem constants
#define MM 1024
#define NN 4096
#define DD 128
#define HH 32
#define PP 4096
#define KVLEN 5120   // PP + MM
#define MN (MM * NN)

// ---------------------------------------------------------------------------
// Scratch (allocation-free rule: __device__ globals)
// ---------------------------------------------------------------------------
__device__ float g_qkv[3ull * MN];                   // q | k | v
__device__ bf16 g_Xhi[MN];
__device__ bf16 g_Xlo[MN];
__device__ bf16 g_Wthi[3ull * NN * NN];              // W transposed [n][k], hi
__device__ bf16 g_Wtlo[3ull * NN * NN];
__device__ bf16 g_Qhi[MN];
__device__ bf16 g_Qlo[MN];
__device__ bf16 g_Khi[(size_t)HH * KVLEN * DD];      // [h][kv][d]
__device__ bf16 g_Klo[(size_t)HH * KVLEN * DD];
__device__ bf16 g_Vthi[(size_t)HH * DD * KVLEN];     // [h][d][kv]
__device__ bf16 g_Vtlo[(size_t)HH * DD * KVLEN];

// ---------------------------------------------------------------------------
// Helpers
// ---------------------------------------------------------------------------
__device__ __forceinline__ uint32_t smem_u32(const void* p) {
    uint32_t a;
    asm("{ .reg .u64 t; cvta.to.shared.u64 t, %1; cvt.u32.u64 %0, t; }" : "=r"(a) : "l"(p));
    return a;
}
__device__ __forceinline__ void ldsm_x4(uint32_t* r, uint32_t addr) {
    asm volatile("ldmatrix.sync.aligned.m8n8.x4.shared.b16 {%0,%1,%2,%3}, [%4];"
                 : "=r"(r[0]), "=r"(r[1]), "=r"(r[2]), "=r"(r[3]) : "r"(addr));
}
__device__ __forceinline__ void ldsm_x2(uint32_t* r, uint32_t addr) {
    asm volatile("ldmatrix.sync.aligned.m8n8.x2.shared.b16 {%0,%1}, [%2];"
                 : "=r"(r[0]), "=r"(r[1]) : "r"(addr));
}
__device__ __forceinline__ void cp16(uint32_t saddr, const void* gaddr) {
    asm volatile("cp.async.cg.shared.global [%0], [%1], 16;"
                 :: "r"(saddr), "l"(gaddr) : "memory");
}
#define CP_COMMIT() asm volatile("cp.async.commit_group;" ::: "memory")
#define CP_WAIT1() asm volatile("cp.async.wait_group 1;" ::: "memory")
#define CP_WAIT0() asm volatile("cp.async.wait_group 0;" ::: "memory")

#define MMA16816(d, a, b)                                              \
    asm volatile(                                                      \
        "mma.sync.aligned.m16n8k16.row.col.f32.bf16.bf16.f32 "         \
        "{%0,%1,%2,%3}, {%4,%5,%6,%7}, {%8,%9}, {%0,%1,%2,%3};"        \
        : "+f"((d)[0]), "+f"((d)[1]), "+f"((d)[2]), "+f"((d)[3])       \
        : "r"((a)[0]), "r"((a)[1]), "r"((a)[2]), "r"((a)[3]),          \
          "r"((b)[0]), "r"((b)[1]))

__device__ __forceinline__ void split2(float x, bf16& h, bf16& l) {
    h = __float2bfloat16(x);
    l = __float2bfloat16(x - __bfloat162float(h));
}
__device__ __forceinline__ uint32_t packsplit_hi(float a, float b) {
    __nv_bfloat162 t(__float2bfloat16(a), __float2bfloat16(b));
    return *(uint32_t*)&t;
}
__device__ __forceinline__ uint32_t packsplit_lo(float a, float b) {
    bf16 ha = __float2bfloat16(a), hb = __float2bfloat16(b);
    __nv_bfloat162 t(__float2bfloat16(a - __bfloat162float(ha)),
                     __float2bfloat16(b - __bfloat162float(hb)));
    return *(uint32_t*)&t;
}

// ---------------------------------------------------------------------------
// RMSNorm over rows of X [1024, 4096], fused bf16 hi/lo split output
// ---------------------------------------------------------------------------
__global__ __launch_bounds__(256) void rmsnorm_split_x(const float* __restrict__ X,
                                                       bf16* __restrict__ hi,
                                                       bf16* __restrict__ lo) {
    int row = blockIdx.x;
    const float4* x4 = (const float4*)(X + (size_t)row * NN);
    float4 v[4];
    float ss = 0.f;
#pragma unroll
    for (int i = 0; i < 4; i++) {
        v[i] = x4[threadIdx.x + i * 256];
        ss += v[i].x * v[i].x + v[i].y * v[i].y + v[i].z * v[i].z + v[i].w * v[i].w;
    }
#pragma unroll
    for (int o = 16; o; o >>= 1) ss += __shfl_xor_sync(0xffffffffu, ss, o);
    __shared__ float wsum[8];
    int warp = threadIdx.x >> 5, lane = threadIdx.x & 31;
    if (lane == 0) wsum[warp] = ss;
    __syncthreads();
    float tot = 0.f;
#pragma unroll
    for (int w = 0; w < 8; w++) tot += wsum[w];
    float s = rsqrtf(tot * (1.0f / (float)NN));
#pragma unroll
    for (int i = 0; i < 4; i++) {
        float a = v[i].x * s, b = v[i].y * s, c = v[i].z * s, d = v[i].w * s;
        size_t off = (size_t)row * NN + (threadIdx.x + i * 256) * 4;
        bf16 h0, h1, h2, h3, l0, l1, l2, l3;
        split2(a, h0, l0); split2(b, h1, l1);
        split2(c, h2, l2); split2(d, h3, l3);
        *(__nv_bfloat162*)(hi + off)     = __nv_bfloat162(h0, h1);
        *(__nv_bfloat162*)(hi + off + 2) = __nv_bfloat162(h2, h3);
        *(__nv_bfloat162*)(lo + off)     = __nv_bfloat162(l0, l1);
        *(__nv_bfloat162*)(lo + off + 2) = __nv_bfloat162(l2, l3);
    }
}

// ---------------------------------------------------------------------------
// Transpose + split W [K, N] fp32 -> Wt hi/lo bf16 [N, K]
// ---------------------------------------------------------------------------
__global__ __launch_bounds__(256) void wsplit_kernel(const float* __restrict__ W,
                                                     bf16* __restrict__ hi,
                                                     bf16* __restrict__ lo) {
    __shared__ float t[32][33];
    int tx = threadIdx.x & 31, ty = threadIdx.x >> 5;
    int n0 = blockIdx.x * 32, k0 = blockIdx.y * 32;
#pragma unroll
    for (int i = 0; i < 4; i++)
        t[ty + i * 8][tx] = W[(size_t)(k0 + ty + i * 8) * NN + n0 + tx];
    __syncthreads();
#pragma unroll
    for (int i = 0; i < 4; i++) {
        float v = t[tx][ty + i * 8];
        bf16 h, l;
        split2(v, h, l);
        size_t off = (size_t)(n0 + ty + i * 8) * NN + k0 + tx;
        hi[off] = h;
        lo[off] = l;
    }
}

// ---------------------------------------------------------------------------
// Per-head RMSNorm over D=128.
// q rows: norm + split -> Qh/Ql (layout [m][h*D+d]).
// k rows: norm + split -> directly into KV cache appended region
//         Kh/Kl[h][PP+m][d]  (no fp32 writeback).
// ---------------------------------------------------------------------------
__global__ __launch_bounds__(256) void qknorm_split_kernel(const float* __restrict__ q,
                                                           const float* __restrict__ k,
                                                           bf16* __restrict__ Qh,
                                                           bf16* __restrict__ Ql,
                                                           bf16* __restrict__ Kh,
                                                           bf16* __restrict__ Kl) {
    int gw = (int)((blockIdx.x * blockDim.x + threadIdx.x) >> 5);
    int lane = threadIdx.x & 31;
    bool isq = (gw < MM * HH);
    int row = isq ? gw : gw - MM * HH;
    const float* src = isq ? q : k;
    float4 a = ((const float4*)(src + (size_t)row * DD))[lane];
    float ss = a.x * a.x + a.y * a.y + a.z * a.z + a.w * a.w;
#pragma unroll
    for (int o = 16; o; o >>= 1) ss += __shfl_xor_sync(0xffffffffu, ss, o);
    float s = rsqrtf(ss * (1.0f / (float)DD));
    a.x *= s; a.y *= s; a.z *= s; a.w *= s;
    bf16 h0, h1, h2, h3, l0, l1, l2, l3;
    split2(a.x, h0, l0); split2(a.y, h1, l1);
    split2(a.z, h2, l2); split2(a.w, h3, l3);
    size_t off;
    bf16 *dh, *dl;
    if (isq) {
        off = (size_t)row * DD + lane * 4;
        dh = Qh; dl = Ql;
    } else {
        int m = row / HH, h = row % HH;
        off = ((size_t)h * KVLEN + PP + m) * DD + lane * 4;
        dh = Kh; dl = Kl;
    }
    *(__nv_bfloat162*)(dh + off)     = __nv_bfloat162(h0, h1);
    *(__nv_bfloat162*)(dh + off + 2) = __nv_bfloat162(h2, h3);
    *(__nv_bfloat162*)(dl + off)     = __nv_bfloat162(l0, l1);
    *(__nv_bfloat162*)(dl + off + 2) = __nv_bfloat162(l2, l3);
}

// ---------------------------------------------------------------------------
// Build K cache hi/lo: CACHE portion only ([h][0..PP][d])
// ---------------------------------------------------------------------------
__global__ __launch_bounds__(256) void build_khl(const float* __restrict__ cacheK,
                                                 bf16* __restrict__ Kh,
                                                 bf16* __restrict__ Kl) {
    size_t e = ((size_t)blockIdx.x * 256 + threadIdx.x) * 4;   // over HH*PP*DD
    int h = (int)(e / ((size_t)PP * DD));
    int rem = (int)(e % ((size_t)PP * DD));
    float4 v = *(const float4*)(cacheK + e);
    bf16 h0, h1, h2, h3, l0, l1, l2, l3;
    split2(v.x, h0, l0); split2(v.y, h1, l1);
    split2(v.z, h2, l2); split2(v.w, h3, l3);
    size_t o = (size_t)h * KVLEN * DD + rem;
    *(__nv_bfloat162*)(Kh + o)     = __nv_bfloat162(h0, h1);
    *(__nv_bfloat162*)(Kh + o + 2) = __nv_bfloat162(h2, h3);
    *(__nv_bfloat162*)(Kl + o)     = __nv_bfloat162(l0, l1);
    *(__nv_bfloat162*)(Kl + o + 2) = __nv_bfloat162(l2, l3);
}

// ---------------------------------------------------------------------------
// Build V^T hi/lo: [h][d][kv]
// ---------------------------------------------------------------------------
__global__ __launch_bounds__(256) void build_vt(const float* __restrict__ cacheV,
                                                const float* __restrict__ vproj,
                                                bf16* __restrict__ Vh,
                                                bf16* __restrict__ Vl) {
    __shared__ float t[32][33];
    int tx = threadIdx.x & 31, ty = threadIdx.x >> 5;
    int kv0 = blockIdx.x * 32, d0 = blockIdx.y * 32, h = blockIdx.z;
#pragma unroll
    for (int i = 0; i < 4; i++) {
        int r = kv0 + ty + i * 8;
        int c = d0 + tx;
        float v = (r < PP)
            ? cacheV[((size_t)h * PP + r) * DD + c]
            : vproj[(size_t)(r - PP) * NN + h * DD + c];
        t[ty + i * 8][tx] = v;
    }
    __syncthreads();
#pragma unroll
    for (int i = 0; i < 4; i++) {
        int d = d0 + ty + i * 8;
        float v = t[tx][ty + i * 8];
        bf16 hh, ll;
        split2(v, hh, ll);
        size_t off = ((size_t)h * DD + d) * KVLEN + kv0 + tx;
        Vh[off] = hh;
        Vl[off] = ll;
    }
}

// ---------------------------------------------------------------------------
// bf16x3 GEMM (mma.sync m16n8k16), 3-slot / 2-in-flight cp.async pipeline,
// one __syncthreads per K-chunk. Term-major MMA order. (R8-proven form.)
// ---------------------------------------------------------------------------
template <int BN, int WN>
__global__ __launch_bounds__(256, 1) void gemm3(
    const bf16* __restrict__ Ah, const bf16* __restrict__ Al,
    const bf16* __restrict__ Bh, const bf16* __restrict__ Bl,
    float* __restrict__ C, int K, int lda, int ldb, int ldc,
    long long sA, long long sB, long long sC) {
    constexpr int BM = 128;
    constexpr int NFR = WN / 8;
    constexpr int PADB = 80;
    constexpr int STG = (2 * BM + 2 * BN) * PADB;
    extern __shared__ char smraw[];

    const int tid = threadIdx.x;
    const int lane = tid & 31, wid = tid >> 5;
    const int wr = wid >> 2, wc = wid & 3;
    const int m0 = blockIdx.y * BM, n0 = blockIdx.x * BN;
    Ah += (long long)blockIdx.z * sA;
    Al += (long long)blockIdx.z * sA;
    Bh += (long long)blockIdx.z * sB;
    Bl += (long long)blockIdx.z * sB;
    C += (long long)blockIdx.z * sC;

    float acc[4][NFR][4];
#pragma unroll
    for (int f = 0; f < 4; f++)
#pragma unroll
        for (int j = 0; j < NFR; j++)
#pragma unroll
            for (int x = 0; x < 4; x++) acc[f][j][x] = 0.f;

    const uint32_t sbase = smem_u32(smraw);
    const uint32_t aoff = (uint32_t)((wr * 64 + (lane & 15)) * PADB + (lane >> 4) * 16);
    const uint32_t boff = (uint32_t)((wc * WN + (lane & 7)) * PADB + ((lane >> 3) & 1) * 16);

    auto issue = [&](int slot, int k0) {
        uint32_t ba = sbase + slot * STG;
        const bf16* pAh = Ah + (size_t)m0 * lda + k0;
        const bf16* pAl = Al + (size_t)m0 * lda + k0;
#pragma unroll
        for (int i = tid; i < BM * 4; i += 256) {
            int r = i >> 2, cb = (i & 3) * 16;
            cp16(ba + r * PADB + cb, (const char*)(pAh + (size_t)r * lda) + cb);
            cp16(ba + BM * PADB + r * PADB + cb, (const char*)(pAl + (size_t)r * lda) + cb);
        }
        uint32_t bb = ba + 2 * BM * PADB;
        const bf16* pBh = Bh + (size_t)n0 * ldb + k0;
        const bf16* pBl = Bl + (size_t)n0 * ldb + k0;
#pragma unroll
        for (int i = tid; i < BN * 4; i += 256) {
            int r = i >> 2, cb = (i & 3) * 16;
            cp16(bb + r * PADB + cb, (const char*)(pBh + (size_t)r * ldb) + cb);
            cp16(bb + BN * PADB + r * PADB + cb, (const char*)(pBl + (size_t)r * ldb) + cb);
        }
        CP_COMMIT();
    };

    const int nch = K >> 5;
    issue(0, 0);
    if (nch > 1) issue(1, 32);

    for (int kc = 0; kc < nch; kc++) {
        if (kc + 1 < nch) { CP_WAIT1(); } else { CP_WAIT0(); }
        __syncthreads();
        if (kc + 2 < nch) issue((kc + 2) % 3, (kc + 2) << 5);

        const uint32_t aH = sbase + (kc % 3) * STG;
        const uint32_t aL = aH + BM * PADB;
        const uint32_t bH = aL + BM * PADB;
        const uint32_t bL = bH + BN * PADB;
#pragma unroll
        for (int ks = 0; ks < 2; ks++) {
            uint32_t ah[4][4], al[4][4];
#pragma unroll
            for (int f = 0; f < 4; f++) {
                uint32_t off = aoff + f * 16 * PADB + ks * 32;
                ldsm_x4(ah[f], aH + off);
                ldsm_x4(al[f], aL + off);
            }
#pragma unroll
            for (int j = 0; j < NFR; j++) {
                uint32_t off = boff + j * 8 * PADB + ks * 32;
                uint32_t bh[2], bl[2];
                ldsm_x2(bh, bH + off);
                ldsm_x2(bl, bL + off);
#pragma unroll
                for (int f = 0; f < 4; f++) MMA16816(acc[f][j], ah[f], bh);
#pragma unroll
                for (int f = 0; f < 4; f++) MMA16816(acc[f][j], ah[f], bl);
#pragma unroll
                for (int f = 0; f < 4; f++) MMA16816(acc[f][j], al[f], bh);
            }
        }
    }
    __syncthreads();

#pragma unroll
    for (int f = 0; f < 4; f++) {
        int row = m0 + wr * 64 + f * 16 + (lane >> 2);
#pragma unroll
        for (int j = 0; j < NFR; j++) {
            int col = n0 + wc * WN + j * 8 + (lane & 3) * 2;
            *(float2*)(C + (size_t)row * ldc + col) = make_float2(acc[f][j][0], acc[f][j][1]);
            *(float2*)(C + (size_t)(row + 8) * ldc + col) = make_float2(acc[f][j][2], acc[f][j][3]);
        }
    }
}

// ---------------------------------------------------------------------------
// Fused flash attention on mma.sync, bf16x3, term-major (R8-proven form),
// Q tile via cp.async overlapped with first KV prefetch.
// ---------------------------------------------------------------------------
#define FA_KPAD 272
#define FA_VPAD 144
#define FA_QB (128 * FA_KPAD)
#define FA_KT (64 * FA_KPAD)
#define FA_VT (128 * FA_VPAD)
#define FA_STG (2 * FA_KT + 2 * FA_VT)
#define FA_SMEM (2 * FA_QB + 2 * FA_STG)   // 212992

__global__ __launch_bounds__(256, 1) void attn_fused(
    const bf16* __restrict__ Qh_, const bf16* __restrict__ Ql_,
    const bf16* __restrict__ Kh_, const bf16* __restrict__ Kl_,
    const bf16* __restrict__ Vh_, const bf16* __restrict__ Vl_,
    float* __restrict__ out) {
    extern __shared__ char sm[];
    const int tid = threadIdx.x, lane = tid & 31, wid = tid >> 5;
    const int m0 = blockIdx.x * 128, h = blockIdx.y;
    const uint32_t sb = smem_u32(sm);

    const bf16* Khh = Kh_ + (size_t)h * KVLEN * DD;
    const bf16* Klh = Kl_ + (size_t)h * KVLEN * DD;
    const bf16* Vhh = Vh_ + (size_t)h * DD * KVLEN;
    const bf16* Vlh = Vl_ + (size_t)h * DD * KVLEN;

    // Q tile via cp.async (folded into the same group as KV prefetch 0)
#pragma unroll
    for (int i = tid; i < 128 * 16; i += 256) {
        int r = i >> 4, c = i & 15;
        size_t go = (size_t)(m0 + r) * NN + h * DD + c * 8;
        cp16(sb + r * FA_KPAD + c * 16, Qh_ + go);
        cp16(sb + FA_QB + r * FA_KPAD + c * 16, Ql_ + go);
    }

    auto issue = [&](int s, int kv0) {
        uint32_t kb = sb + 2 * FA_QB + s * FA_STG;
#pragma unroll
        for (int i = tid; i < 1024; i += 256) {
            int r = i >> 4, c = i & 15;
            size_t go = (size_t)(kv0 + r) * DD + c * 8;
            cp16(kb + r * FA_KPAD + c * 16, Khh + go);
            cp16(kb + FA_KT + r * FA_KPAD + c * 16, Klh + go);
        }
        uint32_t vb = kb + 2 * FA_KT;
#pragma unroll
        for (int i = tid; i < 1024; i += 256) {
            int r = i >> 3, c = i & 7;
            size_t go = (size_t)r * KVLEN + kv0 + c * 8;
            cp16(vb + r * FA_VPAD + c * 16, Vhh + go);
            cp16(vb + FA_VT + r * FA_VPAD + c * 16, Vlh + go);
        }
        CP_COMMIT();
    };

    float oacc[16][4];
#pragma unroll
    for (int j = 0; j < 16; j++)
#pragma unroll
        for (int x = 0; x < 4; x++) oacc[j][x] = 0.f;
    float mrow0 = -INFINITY, mrow8 = -INFINITY;
    float lrow0 = 0.f, lrow8 = 0.f;

    const uint32_t qoff = (uint32_t)((wid * 16 + (lane & 15)) * FA_KPAD + (lane >> 4) * 16);
    const uint32_t koff = (uint32_t)((lane & 7) * FA_KPAD + ((lane >> 3) & 1) * 16);
    const uint32_t voff = (uint32_t)((lane & 7) * FA_VPAD + ((lane >> 3) & 1) * 16);

    issue(0, 0);   // commits Q loads + KV chunk 0 as group 0

    for (int ch = 0; ch < KVLEN / 64; ch++) {
        const int s = ch & 1;
        if (ch + 1 < KVLEN / 64) {
            issue(s ^ 1, (ch + 1) * 64);
            CP_WAIT1();
        } else {
            CP_WAIT0();
        }
        __syncthreads();

        const uint32_t bKh = sb + 2 * FA_QB + s * FA_STG;
        const uint32_t bKl = bKh + FA_KT;
        const uint32_t bVh = bKh + 2 * FA_KT;
        const uint32_t bVl = bVh + FA_VT;

        // S = Q @ K^T, term-major over 8 j-tiles
        float sacc[8][4];
#pragma unroll
        for (int j = 0; j < 8; j++)
#pragma unroll
            for (int x = 0; x < 4; x++) sacc[j][x] = 0.f;
#pragma unroll
        for (int ks = 0; ks < 8; ks++) {
            uint32_t qh[4], ql[4];
            ldsm_x4(qh, sb + qoff + ks * 32);
            ldsm_x4(ql, sb + FA_QB + qoff + ks * 32);
            uint32_t kh[8][2], kl[8][2];
#pragma unroll
            for (int j = 0; j < 8; j++) {
                uint32_t off = koff + j * 8 * FA_KPAD + ks * 32;
                ldsm_x2(kh[j], bKh + off);
                ldsm_x2(kl[j], bKl + off);
            }
#pragma unroll
            for (int j = 0; j < 8; j++) MMA16816(sacc[j], qh, kh[j]);
#pragma unroll
            for (int j = 0; j < 8; j++) MMA16816(sacc[j], qh, kl[j]);
#pragma unroll
            for (int j = 0; j < 8; j++) MMA16816(sacc[j], ql, kh[j]);
        }

        // Online softmax
        float mx0 = -INFINITY, mx8 = -INFINITY;
#pragma unroll
        for (int j = 0; j < 8; j++) {
            mx0 = fmaxf(mx0, fmaxf(sacc[j][0], sacc[j][1]));
            mx8 = fmaxf(mx8, fmaxf(sacc[j][2], sacc[j][3]));
        }
        mx0 = fmaxf(mx0, __shfl_xor_sync(0xffffffffu, mx0, 1));
        mx0 = fmaxf(mx0, __shfl_xor_sync(0xffffffffu, mx0, 2));
        mx8 = fmaxf(mx8, __shfl_xor_sync(0xffffffffu, mx8, 1));
        mx8 = fmaxf(mx8, __shfl_xor_sync(0xffffffffu, mx8, 2));
        float mn0 = fmaxf(mrow0, mx0), mn8 = fmaxf(mrow8, mx8);
        float sc0 = __expf(mrow0 - mn0), sc8 = __expf(mrow8 - mn8);
        mrow0 = mn0; mrow8 = mn8;
        float ps0 = 0.f, ps8 = 0.f;
#pragma unroll
        for (int j = 0; j < 8; j++) {
            sacc[j][0] = __expf(sacc[j][0] - mn0);
            sacc[j][1] = __expf(sacc[j][1] - mn0);
            sacc[j][2] = __expf(sacc[j][2] - mn8);
            sacc[j][3] = __expf(sacc[j][3] - mn8);
            ps0 += sacc[j][0] + sacc[j][1];
            ps8 += sacc[j][2] + sacc[j][3];
        }
        lrow0 = lrow0 * sc0 + ps0;
        lrow8 = lrow8 * sc8 + ps8;
#pragma unroll
        for (int j = 0; j < 16; j++) {
            oacc[j][0] *= sc0; oacc[j][1] *= sc0;
            oacc[j][2] *= sc8; oacc[j][3] *= sc8;
        }

        // P fragments: hi/lo split in regs
        uint32_t ph[4][4], pl[4][4];
#pragma unroll
        for (int kk = 0; kk < 4; kk++) {
            ph[kk][0] = packsplit_hi(sacc[2 * kk][0], sacc[2 * kk][1]);
            ph[kk][1] = packsplit_hi(sacc[2 * kk][2], sacc[2 * kk][3]);
            ph[kk][2] = packsplit_hi(sacc[2 * kk + 1][0], sacc[2 * kk + 1][1]);
            ph[kk][3] = packsplit_hi(sacc[2 * kk + 1][2], sacc[2 * kk + 1][3]);
            pl[kk][0] = packsplit_lo(sacc[2 * kk][0], sacc[2 * kk][1]);
            pl[kk][1] = packsplit_lo(sacc[2 * kk][2], sacc[2 * kk][3]);
            pl[kk][2] = packsplit_lo(sacc[2 * kk + 1][0], sacc[2 * kk + 1][1]);
            pl[kk][3] = packsplit_lo(sacc[2 * kk + 1][2], sacc[2 * kk + 1][3]);
        }

        // O += P @ V^T, term-major in halves of 8 j-tiles
#pragma unroll
        for (int kk = 0; kk < 4; kk++) {
#pragma unroll
            for (int jh = 0; jh < 2; jh++) {
                uint32_t vh[8][2], vl[8][2];
#pragma unroll
                for (int j = 0; j < 8; j++) {
                    uint32_t off = voff + (jh * 8 + j) * 8 * FA_VPAD + kk * 32;
                    ldsm_x2(vh[j], bVh + off);
                    ldsm_x2(vl[j], bVl + off);
                }
#pragma unroll
                for (int j = 0; j < 8; j++) MMA16816(oacc[jh * 8 + j], ph[kk], vh[j]);
#pragma unroll
                for (int j = 0; j < 8; j++) MMA16816(oacc[jh * 8 + j], ph[kk], vl[j]);
#pragma unroll
                for (int j = 0; j < 8; j++) MMA16816(oacc[jh * 8 + j], pl[kk], vh[j]);
            }
        }
        __syncthreads();
    }

    lrow0 += __shfl_xor_sync(0xffffffffu, lrow0, 1);
    lrow0 += __shfl_xor_sync(0xffffffffu, lrow0, 2);
    lrow8 += __shfl_xor_sync(0xffffffffu, lrow8, 1);
    lrow8 += __shfl_xor_sync(0xffffffffu, lrow8, 2);
    float inv0 = 1.0f / lrow0, inv8 = 1.0f / lrow8;
    int r0 = m0 + wid * 16 + (lane >> 2);
#pragma unroll
    for (int j = 0; j < 16; j++) {
        int col = h * DD + j * 8 + (lane & 3) * 2;
        *(float2*)(out + (size_t)r0 * NN + col) =
            make_float2(oacc[j][0] * inv0, oacc[j][1] * inv0);
        *(float2*)(out + (size_t)(r0 + 8) * NN + col) =
            make_float2(oacc[j][2] * inv8, oacc[j][3] * inv8);
    }
}

// ---------------------------------------------------------------------------
extern "C" void kernel_launch(void* const* d_in, const int* in_sizes, int n_in,
                              void* d_out, int out_size) {
    const float* X  = (const float*)d_in[0];
    const float* Wq = (const float*)d_in[1];
    const float* Wk = (const float*)d_in[2];
    const float* Wv = (const float*)d_in[3];
    const float* cK = (const float*)d_in[4];
    const float* cV = (const float*)d_in[5];
    float* out = (float*)d_out;

    float* qkv;
    bf16 *Xhi, *Xlo, *Wthi, *Wtlo, *Qhi, *Qlo, *Khi, *Klo, *Vthi, *Vtlo;
    cudaGetSymbolAddress((void**)&qkv, g_qkv);
    cudaGetSymbolAddress((void**)&Xhi, g_Xhi);
    cudaGetSymbolAddress((void**)&Xlo, g_Xlo);
    cudaGetSymbolAddress((void**)&Wthi, g_Wthi);
    cudaGetSymbolAddress((void**)&Wtlo, g_Wtlo);
    cudaGetSymbolAddress((void**)&Qhi, g_Qhi);
    cudaGetSymbolAddress((void**)&Qlo, g_Qlo);
    cudaGetSymbolAddress((void**)&Khi, g_Khi);
    cudaGetSymbolAddress((void**)&Klo, g_Klo);
    cudaGetSymbolAddress((void**)&Vthi, g_Vthi);
    cudaGetSymbolAddress((void**)&Vtlo, g_Vtlo);

    float* q = qkv;
    float* k = qkv + (size_t)MN;
    float* v = qkv + 2ull * MN;

    const int SM256 = 3 * (2 * 128 + 2 * 256) * 80;   // 184320 (3 slots)
    cudaFuncSetAttribute(gemm3<256, 64>, cudaFuncAttributeMaxDynamicSharedMemorySize, SM256);
    cudaFuncSetAttribute(attn_fused, cudaFuncAttributeMaxDynamicSharedMemorySize, FA_SMEM);

    // 1) RMSNorm X + split (fused)
    rmsnorm_split_x<<<MM, 256>>>(X, Xhi, Xlo);

    // 2) W transpose+split
    dim3 wgrid(NN / 32, NN / 32);
    wsplit_kernel<<<wgrid, 256>>>(Wq, Wthi + 0ull * NN * NN, Wtlo + 0ull * NN * NN);
    wsplit_kernel<<<wgrid, 256>>>(Wk, Wthi + 1ull * NN * NN, Wtlo + 1ull * NN * NN);
    wsplit_kernel<<<wgrid, 256>>>(Wv, Wthi + 2ull * NN * NN, Wtlo + 2ull * NN * NN);

    // 3) QKV = Xn @ W  (batched z=3, R8-proven)
    gemm3<256, 64><<<dim3(NN / 256, MM / 128, 3), 256, SM256>>>(
        Xhi, Xlo, Wthi, Wtlo, qkv, NN, NN, NN, NN,
        0LL, (long long)NN * NN, (long long)MN);

    // 4) qk-norm: q -> Qhi/Qlo; k -> Khi/Klo appended region directly
    qknorm_split_kernel<<<(2 * MM * HH * 32) / 256, 256>>>(q, k, Qhi, Qlo, Khi, Klo);

    // 5) KV cache conversions (cache-only K; full V^T)
    build_khl<<<(int)((size_t)HH * PP * DD / 1024), 256>>>(cK, Khi, Klo);
    build_vt<<<dim3(KVLEN / 32, DD / 32, HH), 256>>>(cV, v, Vthi, Vtlo);

    // 6) fused flash attention -> d_out
    attn_fused<<<dim3(MM / 128, HH), 256, FA_SMEM>>>(
        Qhi, Qlo, Khi, Klo, Vthi, Vtlo, out);
}

// round 12
// speedup vs baseline: 1.3134x; 1.2747x over previous
#include <cuda_runtime.h>
#include <cuda_bf16.h>
#include <cuda_fp16.h>
#include <math.h>
#include <stdint.h>

typedef __nv_bfloat16 bf16;
typedef __half fp16;

// Problem constants
#define MM 1024
#define NN 4096
#define DD 128
#define HH 32
#define PP 4096
#define KVLEN 5120   // PP + MM
#define MN (MM * NN)

// ---------------------------------------------------------------------------
// Scratch (allocation-free rule: __device__ globals)
// ---------------------------------------------------------------------------
__device__ float g_qkv[3ull * MN];                   // q | k | v (fp32 gemm out)
__device__ bf16 g_Xhi[MN];
__device__ bf16 g_Xlo[MN];
__device__ fp16 g_Xh[MN];
__device__ bf16 g_Wthi[2ull * NN * NN];              // Wq,Wk transposed, hi
__device__ bf16 g_Wtlo[2ull * NN * NN];
__device__ fp16 g_Wthv[(size_t)NN * NN];             // Wv transposed fp16
__device__ bf16 g_Qhi[MN];
__device__ bf16 g_Qlo[MN];
__device__ bf16 g_Khi[(size_t)HH * KVLEN * DD];      // [h][kv][d]
__device__ bf16 g_Klo[(size_t)HH * KVLEN * DD];
__device__ fp16 g_Vth[(size_t)HH * DD * KVLEN];      // [h][d][kv] fp16

// ---------------------------------------------------------------------------
// Helpers
// ---------------------------------------------------------------------------
__device__ __forceinline__ uint32_t smem_u32(const void* p) {
    uint32_t a;
    asm("{ .reg .u64 t; cvta.to.shared.u64 t, %1; cvt.u32.u64 %0, t; }" : "=r"(a) : "l"(p));
    return a;
}
__device__ __forceinline__ void ldsm_x4(uint32_t* r, uint32_t addr) {
    asm volatile("ldmatrix.sync.aligned.m8n8.x4.shared.b16 {%0,%1,%2,%3}, [%4];"
                 : "=r"(r[0]), "=r"(r[1]), "=r"(r[2]), "=r"(r[3]) : "r"(addr));
}
__device__ __forceinline__ void ldsm_x2(uint32_t* r, uint32_t addr) {
    asm volatile("ldmatrix.sync.aligned.m8n8.x2.shared.b16 {%0,%1}, [%2];"
                 : "=r"(r[0]), "=r"(r[1]) : "r"(addr));
}
__device__ __forceinline__ void cp16(uint32_t saddr, const void* gaddr) {
    asm volatile("cp.async.cg.shared.global [%0], [%1], 16;"
                 :: "r"(saddr), "l"(gaddr) : "memory");
}
#define CP_COMMIT() asm volatile("cp.async.commit_group;" ::: "memory")
#define CP_WAIT1() asm volatile("cp.async.wait_group 1;" ::: "memory")
#define CP_WAIT0() asm volatile("cp.async.wait_group 0;" ::: "memory")

// bf16 inputs, fp32 acc
#define MMA_BF(d, a, b)                                                \
    asm volatile(                                                      \
        "mma.sync.aligned.m16n8k16.row.col.f32.bf16.bf16.f32 "         \
        "{%0,%1,%2,%3}, {%4,%5,%6,%7}, {%8,%9}, {%0,%1,%2,%3};"        \
        : "+f"((d)[0]), "+f"((d)[1]), "+f"((d)[2]), "+f"((d)[3])       \
        : "r"((a)[0]), "r"((a)[1]), "r"((a)[2]), "r"((a)[3]),          \
          "r"((b)[0]), "r"((b)[1]))
// fp16 inputs, fp32 acc
#define MMA_FP(d, a, b)                                                \
    asm volatile(                                                      \
        "mma.sync.aligned.m16n8k16.row.col.f32.f16.f16.f32 "           \
        "{%0,%1,%2,%3}, {%4,%5,%6,%7}, {%8,%9}, {%0,%1,%2,%3};"        \
        : "+f"((d)[0]), "+f"((d)[1]), "+f"((d)[2]), "+f"((d)[3])       \
        : "r"((a)[0]), "r"((a)[1]), "r"((a)[2]), "r"((a)[3]),          \
          "r"((b)[0]), "r"((b)[1]))

__device__ __forceinline__ void split2(float x, bf16& h, bf16& l) {
    h = __float2bfloat16(x);
    l = __float2bfloat16(x - __bfloat162float(h));
}
__device__ __forceinline__ uint32_t packh2(float a, float b) {
    __half2 t = __floats2half2_rn(a, b);
    return *(uint32_t*)&t;
}

// ---------------------------------------------------------------------------
// RMSNorm over rows of X: outputs bf16 hi/lo (for q,k GEMM) + fp16 (for v GEMM)
// ---------------------------------------------------------------------------
__global__ __launch_bounds__(256) void rmsnorm_split_x(const float* __restrict__ X,
                                                       bf16* __restrict__ hi,
                                                       bf16* __restrict__ lo,
                                                       fp16* __restrict__ xh) {
    int row = blockIdx.x;
    const float4* x4 = (const float4*)(X + (size_t)row * NN);
    float4 v[4];
    float ss = 0.f;
#pragma unroll
    for (int i = 0; i < 4; i++) {
        v[i] = x4[threadIdx.x + i * 256];
        ss += v[i].x * v[i].x + v[i].y * v[i].y + v[i].z * v[i].z + v[i].w * v[i].w;
    }
#pragma unroll
    for (int o = 16; o; o >>= 1) ss += __shfl_xor_sync(0xffffffffu, ss, o);
    __shared__ float wsum[8];
    int warp = threadIdx.x >> 5, lane = threadIdx.x & 31;
    if (lane == 0) wsum[warp] = ss;
    __syncthreads();
    float tot = 0.f;
#pragma unroll
    for (int w = 0; w < 8; w++) tot += wsum[w];
    float s = rsqrtf(tot * (1.0f / (float)NN));
#pragma unroll
    for (int i = 0; i < 4; i++) {
        float a = v[i].x * s, b = v[i].y * s, c = v[i].z * s, d = v[i].w * s;
        size_t off = (size_t)row * NN + (threadIdx.x + i * 256) * 4;
        bf16 h0, h1, h2, h3, l0, l1, l2, l3;
        split2(a, h0, l0); split2(b, h1, l1);
        split2(c, h2, l2); split2(d, h3, l3);
        *(__nv_bfloat162*)(hi + off)     = __nv_bfloat162(h0, h1);
        *(__nv_bfloat162*)(hi + off + 2) = __nv_bfloat162(h2, h3);
        *(__nv_bfloat162*)(lo + off)     = __nv_bfloat162(l0, l1);
        *(__nv_bfloat162*)(lo + off + 2) = __nv_bfloat162(l2, l3);
        *(__half2*)(xh + off)     = __floats2half2_rn(a, b);
        *(__half2*)(xh + off + 2) = __floats2half2_rn(c, d);
    }
}

// ---------------------------------------------------------------------------
// Transpose + split W -> bf16 hi/lo [N, K]
// ---------------------------------------------------------------------------
__global__ __launch_bounds__(256) void wsplit_kernel(const float* __restrict__ W,
                                                     bf16* __restrict__ hi,
                                                     bf16* __restrict__ lo) {
    __shared__ float t[32][33];
    int tx = threadIdx.x & 31, ty = threadIdx.x >> 5;
    int n0 = blockIdx.x * 32, k0 = blockIdx.y * 32;
#pragma unroll
    for (int i = 0; i < 4; i++)
        t[ty + i * 8][tx] = W[(size_t)(k0 + ty + i * 8) * NN + n0 + tx];
    __syncthreads();
#pragma unroll
    for (int i = 0; i < 4; i++) {
        float v = t[tx][ty + i * 8];
        bf16 h, l;
        split2(v, h, l);
        size_t off = (size_t)(n0 + ty + i * 8) * NN + k0 + tx;
        hi[off] = h;
        lo[off] = l;
    }
}

// ---------------------------------------------------------------------------
// Transpose + convert W -> fp16 [N, K]
// ---------------------------------------------------------------------------
__global__ __launch_bounds__(256) void wconv_kernel(const float* __restrict__ W,
                                                    fp16* __restrict__ out) {
    __shared__ float t[32][33];
    int tx = threadIdx.x & 31, ty = threadIdx.x >> 5;
    int n0 = blockIdx.x * 32, k0 = blockIdx.y * 32;
#pragma unroll
    for (int i = 0; i < 4; i++)
        t[ty + i * 8][tx] = W[(size_t)(k0 + ty + i * 8) * NN + n0 + tx];
    __syncthreads();
#pragma unroll
    for (int i = 0; i < 4; i++) {
        size_t off = (size_t)(n0 + ty + i * 8) * NN + k0 + tx;
        out[off] = __float2half_rn(t[tx][ty + i * 8]);
    }
}

// ---------------------------------------------------------------------------
// Per-head RMSNorm over D=128.
// q rows: norm + bf16 split -> Qhi/Qlo. k rows: norm + bf16 split -> KV cache
// appended region Khi/Klo[h][PP+m][d].
// ---------------------------------------------------------------------------
__global__ __launch_bounds__(256) void qknorm_split_kernel(const float* __restrict__ q,
                                                           const float* __restrict__ k,
                                                           bf16* __restrict__ Qh,
                                                           bf16* __restrict__ Ql,
                                                           bf16* __restrict__ Kh,
                                                           bf16* __restrict__ Kl) {
    int gw = (int)((blockIdx.x * blockDim.x + threadIdx.x) >> 5);
    int lane = threadIdx.x & 31;
    bool isq = (gw < MM * HH);
    int row = isq ? gw : gw - MM * HH;
    const float* src = isq ? q : k;
    float4 a = ((const float4*)(src + (size_t)row * DD))[lane];
    float ss = a.x * a.x + a.y * a.y + a.z * a.z + a.w * a.w;
#pragma unroll
    for (int o = 16; o; o >>= 1) ss += __shfl_xor_sync(0xffffffffu, ss, o);
    float s = rsqrtf(ss * (1.0f / (float)DD));
    a.x *= s; a.y *= s; a.z *= s; a.w *= s;
    bf16 h0, h1, h2, h3, l0, l1, l2, l3;
    split2(a.x, h0, l0); split2(a.y, h1, l1);
    split2(a.z, h2, l2); split2(a.w, h3, l3);
    size_t off;
    bf16 *dh, *dl;
    if (isq) {
        off = (size_t)row * DD + lane * 4;
        dh = Qh; dl = Ql;
    } else {
        int m = row / HH, h = row % HH;
        off = ((size_t)h * KVLEN + PP + m) * DD + lane * 4;
        dh = Kh; dl = Kl;
    }
    *(__nv_bfloat162*)(dh + off)     = __nv_bfloat162(h0, h1);
    *(__nv_bfloat162*)(dh + off + 2) = __nv_bfloat162(h2, h3);
    *(__nv_bfloat162*)(dl + off)     = __nv_bfloat162(l0, l1);
    *(__nv_bfloat162*)(dl + off + 2) = __nv_bfloat162(l2, l3);
}

// ---------------------------------------------------------------------------
// Build K cache hi/lo: CACHE portion only
// ---------------------------------------------------------------------------
__global__ __launch_bounds__(256) void build_khl(const float* __restrict__ cacheK,
                                                 bf16* __restrict__ Kh,
                                                 bf16* __restrict__ Kl) {
    size_t e = ((size_t)blockIdx.x * 256 + threadIdx.x) * 4;
    int h = (int)(e / ((size_t)PP * DD));
    int rem = (int)(e % ((size_t)PP * DD));
    float4 v = *(const float4*)(cacheK + e);
    bf16 h0, h1, h2, h3, l0, l1, l2, l3;
    split2(v.x, h0, l0); split2(v.y, h1, l1);
    split2(v.z, h2, l2); split2(v.w, h3, l3);
    size_t o = (size_t)h * KVLEN * DD + rem;
    *(__nv_bfloat162*)(Kh + o)     = __nv_bfloat162(h0, h1);
    *(__nv_bfloat162*)(Kh + o + 2) = __nv_bfloat162(h2, h3);
    *(__nv_bfloat162*)(Kl + o)     = __nv_bfloat162(l0, l1);
    *(__nv_bfloat162*)(Kl + o + 2) = __nv_bfloat162(l2, l3);
}

// ---------------------------------------------------------------------------
// Build V^T fp16: [h][d][kv]
// ---------------------------------------------------------------------------
__global__ __launch_bounds__(256) void build_vt(const float* __restrict__ cacheV,
                                                const float* __restrict__ vproj,
                                                fp16* __restrict__ Vh) {
    __shared__ float t[32][33];
    int tx = threadIdx.x & 31, ty = threadIdx.x >> 5;
    int kv0 = blockIdx.x * 32, d0 = blockIdx.y * 32, h = blockIdx.z;
#pragma unroll
    for (int i = 0; i < 4; i++) {
        int r = kv0 + ty + i * 8;
        int c = d0 + tx;
        float v = (r < PP)
            ? cacheV[((size_t)h * PP + r) * DD + c]
            : vproj[(size_t)(r - PP) * NN + h * DD + c];
        t[ty + i * 8][tx] = v;
    }
    __syncthreads();
#pragma unroll
    for (int i = 0; i < 4; i++) {
        int d = d0 + ty + i * 8;
        size_t off = ((size_t)h * DD + d) * KVLEN + kv0 + tx;
        Vh[off] = __float2half_rn(t[tx][ty + i * 8]);
    }
}

// ---------------------------------------------------------------------------
// bf16x3 GEMM (R8/R10-proven form) — used for q,k projections (batch z)
// ---------------------------------------------------------------------------
template <int BN, int WN>
__global__ __launch_bounds__(256, 1) void gemm3(
    const bf16* __restrict__ Ah, const bf16* __restrict__ Al,
    const bf16* __restrict__ Bh, const bf16* __restrict__ Bl,
    float* __restrict__ C, int K, int lda, int ldb, int ldc,
    long long sA, long long sB, long long sC) {
    constexpr int BM = 128;
    constexpr int NFR = WN / 8;
    constexpr int PADB = 80;
    constexpr int STG = (2 * BM + 2 * BN) * PADB;
    extern __shared__ char smraw[];

    const int tid = threadIdx.x;
    const int lane = tid & 31, wid = tid >> 5;
    const int wr = wid >> 2, wc = wid & 3;
    const int m0 = blockIdx.y * BM, n0 = blockIdx.x * BN;
    Ah += (long long)blockIdx.z * sA;
    Al += (long long)blockIdx.z * sA;
    Bh += (long long)blockIdx.z * sB;
    Bl += (long long)blockIdx.z * sB;
    C += (long long)blockIdx.z * sC;

    float acc[4][NFR][4];
#pragma unroll
    for (int f = 0; f < 4; f++)
#pragma unroll
        for (int j = 0; j < NFR; j++)
#pragma unroll
            for (int x = 0; x < 4; x++) acc[f][j][x] = 0.f;

    const uint32_t sbase = smem_u32(smraw);
    const uint32_t aoff = (uint32_t)((wr * 64 + (lane & 15)) * PADB + (lane >> 4) * 16);
    const uint32_t boff = (uint32_t)((wc * WN + (lane & 7)) * PADB + ((lane >> 3) & 1) * 16);

    auto issue = [&](int slot, int k0) {
        uint32_t ba = sbase + slot * STG;
        const bf16* pAh = Ah + (size_t)m0 * lda + k0;
        const bf16* pAl = Al + (size_t)m0 * lda + k0;
#pragma unroll
        for (int i = tid; i < BM * 4; i += 256) {
            int r = i >> 2, cb = (i & 3) * 16;
            cp16(ba + r * PADB + cb, (const char*)(pAh + (size_t)r * lda) + cb);
            cp16(ba + BM * PADB + r * PADB + cb, (const char*)(pAl + (size_t)r * lda) + cb);
        }
        uint32_t bb = ba + 2 * BM * PADB;
        const bf16* pBh = Bh + (size_t)n0 * ldb + k0;
        const bf16* pBl = Bl + (size_t)n0 * ldb + k0;
#pragma unroll
        for (int i = tid; i < BN * 4; i += 256) {
            int r = i >> 2, cb = (i & 3) * 16;
            cp16(bb + r * PADB + cb, (const char*)(pBh + (size_t)r * ldb) + cb);
            cp16(bb + BN * PADB + r * PADB + cb, (const char*)(pBl + (size_t)r * ldb) + cb);
        }
        CP_COMMIT();
    };

    const int nch = K >> 5;
    issue(0, 0);
    if (nch > 1) issue(1, 32);

    for (int kc = 0; kc < nch; kc++) {
        if (kc + 1 < nch) { CP_WAIT1(); } else { CP_WAIT0(); }
        __syncthreads();
        if (kc + 2 < nch) issue((kc + 2) % 3, (kc + 2) << 5);

        const uint32_t aH = sbase + (kc % 3) * STG;
        const uint32_t aL = aH + BM * PADB;
        const uint32_t bH = aL + BM * PADB;
        const uint32_t bL = bH + BN * PADB;
#pragma unroll
        for (int ks = 0; ks < 2; ks++) {
            uint32_t ah[4][4], al[4][4];
#pragma unroll
            for (int f = 0; f < 4; f++) {
                uint32_t off = aoff + f * 16 * PADB + ks * 32;
                ldsm_x4(ah[f], aH + off);
                ldsm_x4(al[f], aL + off);
            }
#pragma unroll
            for (int j = 0; j < NFR; j++) {
                uint32_t off = boff + j * 8 * PADB + ks * 32;
                uint32_t bh[2], bl[2];
                ldsm_x2(bh, bH + off);
                ldsm_x2(bl, bL + off);
#pragma unroll
                for (int f = 0; f < 4; f++) MMA_BF(acc[f][j], ah[f], bh);
#pragma unroll
                for (int f = 0; f < 4; f++) MMA_BF(acc[f][j], ah[f], bl);
#pragma unroll
                for (int f = 0; f < 4; f++) MMA_BF(acc[f][j], al[f], bh);
            }
        }
    }
    __syncthreads();

#pragma unroll
    for (int f = 0; f < 4; f++) {
        int row = m0 + wr * 64 + f * 16 + (lane >> 2);
#pragma unroll
        for (int j = 0; j < NFR; j++) {
            int col = n0 + wc * WN + j * 8 + (lane & 3) * 2;
            *(float2*)(C + (size_t)row * ldc + col) = make_float2(acc[f][j][0], acc[f][j][1]);
            *(float2*)(C + (size_t)(row + 8) * ldc + col) = make_float2(acc[f][j][2], acc[f][j][3]);
        }
    }
}

// ---------------------------------------------------------------------------
// fp16 single-term GEMM (R11 form) — used for v projection
// ---------------------------------------------------------------------------
template <int BN, int WN>
__global__ __launch_bounds__(256, 1) void gemmh(
    const fp16* __restrict__ A, const fp16* __restrict__ B,
    float* __restrict__ C, int K, int lda, int ldb, int ldc) {
    constexpr int BM = 128;
    constexpr int NFR = WN / 8;
    constexpr int PADB = 80;
    constexpr int STG = (BM + BN) * PADB;
    extern __shared__ char smraw[];

    const int tid = threadIdx.x;
    const int lane = tid & 31, wid = tid >> 5;
    const int wr = wid >> 2, wc = wid & 3;
    const int m0 = blockIdx.y * BM, n0 = blockIdx.x * BN;

    float acc[4][NFR][4];
#pragma unroll
    for (int f = 0; f < 4; f++)
#pragma unroll
        for (int j = 0; j < NFR; j++)
#pragma unroll
            for (int x = 0; x < 4; x++) acc[f][j][x] = 0.f;

    const uint32_t sbase = smem_u32(smraw);
    const uint32_t aoff = (uint32_t)((wr * 64 + (lane & 15)) * PADB + (lane >> 4) * 16);
    const uint32_t boff = (uint32_t)((wc * WN + (lane & 7)) * PADB + ((lane >> 3) & 1) * 16);

    auto issue = [&](int slot, int k0) {
        uint32_t ba = sbase + slot * STG;
        const fp16* pA = A + (size_t)m0 * lda + k0;
#pragma unroll
        for (int i = tid; i < BM * 4; i += 256) {
            int r = i >> 2, cb = (i & 3) * 16;
            cp16(ba + r * PADB + cb, (const char*)(pA + (size_t)r * lda) + cb);
        }
        uint32_t bb = ba + BM * PADB;
        const fp16* pB = B + (size_t)n0 * ldb + k0;
#pragma unroll
        for (int i = tid; i < BN * 4; i += 256) {
            int r = i >> 2, cb = (i & 3) * 16;
            cp16(bb + r * PADB + cb, (const char*)(pB + (size_t)r * ldb) + cb);
        }
        CP_COMMIT();
    };

    const int nch = K >> 5;
    issue(0, 0);
    if (nch > 1) issue(1, 32);

    for (int kc = 0; kc < nch; kc++) {
        if (kc + 1 < nch) { CP_WAIT1(); } else { CP_WAIT0(); }
        __syncthreads();
        if (kc + 2 < nch) issue((kc + 2) % 3, (kc + 2) << 5);

        const uint32_t aB = sbase + (kc % 3) * STG;
        const uint32_t bB = aB + BM * PADB;
#pragma unroll
        for (int ks = 0; ks < 2; ks++) {
            uint32_t af[4][4];
#pragma unroll
            for (int f = 0; f < 4; f++)
                ldsm_x4(af[f], aB + aoff + f * 16 * PADB + ks * 32);
#pragma unroll
            for (int j = 0; j < NFR; j++) {
                uint32_t bf[2];
                ldsm_x2(bf, bB + boff + j * 8 * PADB + ks * 32);
#pragma unroll
                for (int f = 0; f < 4; f++) MMA_FP(acc[f][j], af[f], bf);
            }
        }
    }
    __syncthreads();

#pragma unroll
    for (int f = 0; f < 4; f++) {
        int row = m0 + wr * 64 + f * 16 + (lane >> 2);
#pragma unroll
        for (int j = 0; j < NFR; j++) {
            int col = n0 + wc * WN + j * 8 + (lane & 3) * 2;
            *(float2*)(C + (size_t)row * ldc + col) = make_float2(acc[f][j][0], acc[f][j][1]);
            *(float2*)(C + (size_t)(row + 8) * ldc + col) = make_float2(acc[f][j][2], acc[f][j][3]);
        }
    }
}

// ---------------------------------------------------------------------------
// Fused flash attention: S = QK^T in bf16x3 (accurate), PV in single fp16.
// Block: 128 q-rows x 1 head. 8 warps x 16 rows. KV chunks of 64, 2 stages.
// ---------------------------------------------------------------------------
#define FA_KPAD 272
#define FA_VPAD 144
#define FA_QB (128 * FA_KPAD)              // 34816
#define FA_KT (64 * FA_KPAD)               // 17408
#define FA_VT (128 * FA_VPAD)              // 18432
#define FA_STG (2 * FA_KT + FA_VT)         // 53248
#define FA_SMEM (2 * FA_QB + 2 * FA_STG)   // 176128

__global__ __launch_bounds__(256, 1) void attn_fused(
    const bf16* __restrict__ Qh_, const bf16* __restrict__ Ql_,
    const bf16* __restrict__ Kh_, const bf16* __restrict__ Kl_,
    const fp16* __restrict__ Vh_, float* __restrict__ out) {
    extern __shared__ char sm[];
    const int tid = threadIdx.x, lane = tid & 31, wid = tid >> 5;
    const int m0 = blockIdx.x * 128, h = blockIdx.y;
    const uint32_t sb = smem_u32(sm);

    const bf16* Khh = Kh_ + (size_t)h * KVLEN * DD;
    const bf16* Klh = Kl_ + (size_t)h * KVLEN * DD;
    const fp16* Vhh = Vh_ + (size_t)h * DD * KVLEN;

    // Q tile (hi/lo) via cp.async, folded into group 0 with KV prefetch
#pragma unroll
    for (int i = tid; i < 128 * 16; i += 256) {
        int r = i >> 4, c = i & 15;
        size_t go = (size_t)(m0 + r) * NN + h * DD + c * 8;
        cp16(sb + r * FA_KPAD + c * 16, Qh_ + go);
        cp16(sb + FA_QB + r * FA_KPAD + c * 16, Ql_ + go);
    }

    auto issue = [&](int s, int kv0) {
        uint32_t kb = sb + 2 * FA_QB + s * FA_STG;
#pragma unroll
        for (int i = tid; i < 1024; i += 256) {
            int r = i >> 4, c = i & 15;
            size_t go = (size_t)(kv0 + r) * DD + c * 8;
            cp16(kb + r * FA_KPAD + c * 16, Khh + go);
            cp16(kb + FA_KT + r * FA_KPAD + c * 16, Klh + go);
        }
        uint32_t vb = kb + 2 * FA_KT;
#pragma unroll
        for (int i = tid; i < 1024; i += 256) {
            int r = i >> 3, c = i & 7;
            cp16(vb + r * FA_VPAD + c * 16, Vhh + (size_t)r * KVLEN + kv0 + c * 8);
        }
        CP_COMMIT();
    };

    float oacc[16][4];
#pragma unroll
    for (int j = 0; j < 16; j++)
#pragma unroll
        for (int x = 0; x < 4; x++) oacc[j][x] = 0.f;
    float mrow0 = -INFINITY, mrow8 = -INFINITY;
    float lrow0 = 0.f, lrow8 = 0.f;

    const uint32_t qoff = (uint32_t)((wid * 16 + (lane & 15)) * FA_KPAD + (lane >> 4) * 16);
    const uint32_t koff = (uint32_t)((lane & 7) * FA_KPAD + ((lane >> 3) & 1) * 16);
    const uint32_t voff = (uint32_t)((lane & 7) * FA_VPAD + ((lane >> 3) & 1) * 16);

    issue(0, 0);

    for (int ch = 0; ch < KVLEN / 64; ch++) {
        const int s = ch & 1;
        if (ch + 1 < KVLEN / 64) {
            issue(s ^ 1, (ch + 1) * 64);
            CP_WAIT1();
        } else {
            CP_WAIT0();
        }
        __syncthreads();

        const uint32_t bKh = sb + 2 * FA_QB + s * FA_STG;
        const uint32_t bKl = bKh + FA_KT;
        const uint32_t bV = bKh + 2 * FA_KT;

        // S = Q @ K^T, bf16x3 term-major
        float sacc[8][4];
#pragma unroll
        for (int j = 0; j < 8; j++)
#pragma unroll
            for (int x = 0; x < 4; x++) sacc[j][x] = 0.f;
#pragma unroll
        for (int ks = 0; ks < 8; ks++) {
            uint32_t qh[4], ql[4];
            ldsm_x4(qh, sb + qoff + ks * 32);
            ldsm_x4(ql, sb + FA_QB + qoff + ks * 32);
            uint32_t kh[8][2], kl[8][2];
#pragma unroll
            for (int j = 0; j < 8; j++) {
                uint32_t off = koff + j * 8 * FA_KPAD + ks * 32;
                ldsm_x2(kh[j], bKh + off);
                ldsm_x2(kl[j], bKl + off);
            }
#pragma unroll
            for (int j = 0; j < 8; j++) MMA_BF(sacc[j], qh, kh[j]);
#pragma unroll
            for (int j = 0; j < 8; j++) MMA_BF(sacc[j], qh, kl[j]);
#pragma unroll
            for (int j = 0; j < 8; j++) MMA_BF(sacc[j], ql, kh[j]);
        }

        // Online softmax
        float mx0 = -INFINITY, mx8 = -INFINITY;
#pragma unroll
        for (int j = 0; j < 8; j++) {
            mx0 = fmaxf(mx0, fmaxf(sacc[j][0], sacc[j][1]));
            mx8 = fmaxf(mx8, fmaxf(sacc[j][2], sacc[j][3]));
        }
        mx0 = fmaxf(mx0, __shfl_xor_sync(0xffffffffu, mx0, 1));
        mx0 = fmaxf(mx0, __shfl_xor_sync(0xffffffffu, mx0, 2));
        mx8 = fmaxf(mx8, __shfl_xor_sync(0xffffffffu, mx8, 1));
        mx8 = fmaxf(mx8, __shfl_xor_sync(0xffffffffu, mx8, 2));
        float mn0 = fmaxf(mrow0, mx0), mn8 = fmaxf(mrow8, mx8);
        float sc0 = __expf(mrow0 - mn0), sc8 = __expf(mrow8 - mn8);
        mrow0 = mn0; mrow8 = mn8;
        float ps0 = 0.f, ps8 = 0.f;
#pragma unroll
        for (int j = 0; j < 8; j++) {
            sacc[j][0] = __expf(sacc[j][0] - mn0);
            sacc[j][1] = __expf(sacc[j][1] - mn0);
            sacc[j][2] = __expf(sacc[j][2] - mn8);
            sacc[j][3] = __expf(sacc[j][3] - mn8);
            ps0 += sacc[j][0] + sacc[j][1];
            ps8 += sacc[j][2] + sacc[j][3];
        }
        lrow0 = lrow0 * sc0 + ps0;
        lrow8 = lrow8 * sc8 + ps8;
#pragma unroll
        for (int j = 0; j < 16; j++) {
            oacc[j][0] *= sc0; oacc[j][1] *= sc0;
            oacc[j][2] *= sc8; oacc[j][3] *= sc8;
        }

        // P fragments (A-frag layout), single fp16 — p in [0,1], eps 6e-5
        uint32_t pf[4][4];
#pragma unroll
        for (int kk = 0; kk < 4; kk++) {
            pf[kk][0] = packh2(sacc[2 * kk][0], sacc[2 * kk][1]);
            pf[kk][1] = packh2(sacc[2 * kk][2], sacc[2 * kk][3]);
            pf[kk][2] = packh2(sacc[2 * kk + 1][0], sacc[2 * kk + 1][1]);
            pf[kk][3] = packh2(sacc[2 * kk + 1][2], sacc[2 * kk + 1][3]);
        }

        // O += P @ V^T, single-term fp16
#pragma unroll
        for (int kk = 0; kk < 4; kk++) {
#pragma unroll
            for (int jh = 0; jh < 2; jh++) {
                uint32_t vf[8][2];
#pragma unroll
                for (int j = 0; j < 8; j++)
                    ldsm_x2(vf[j], bV + voff + (jh * 8 + j) * 8 * FA_VPAD + kk * 32);
#pragma unroll
                for (int j = 0; j < 8; j++) MMA_FP(oacc[jh * 8 + j], pf[kk], vf[j]);
            }
        }
        __syncthreads();
    }

    lrow0 += __shfl_xor_sync(0xffffffffu, lrow0, 1);
    lrow0 += __shfl_xor_sync(0xffffffffu, lrow0, 2);
    lrow8 += __shfl_xor_sync(0xffffffffu, lrow8, 1);
    lrow8 += __shfl_xor_sync(0xffffffffu, lrow8, 2);
    float inv0 = 1.0f / lrow0, inv8 = 1.0f / lrow8;
    int r0 = m0 + wid * 16 + (lane >> 2);
#pragma unroll
    for (int j = 0; j < 16; j++) {
        int col = h * DD + j * 8 + (lane & 3) * 2;
        *(float2*)(out + (size_t)r0 * NN + col) =
            make_float2(oacc[j][0] * inv0, oacc[j][1] * inv0);
        *(float2*)(out + (size_t)(r0 + 8) * NN + col) =
            make_float2(oacc[j][2] * inv8, oacc[j][3] * inv8);
    }
}

// ---------------------------------------------------------------------------
extern "C" void kernel_launch(void* const* d_in, const int* in_sizes, int n_in,
                              void* d_out, int out_size) {
    const float* X  = (const float*)d_in[0];
    const float* Wq = (const float*)d_in[1];
    const float* Wk = (const float*)d_in[2];
    const float* Wv = (const float*)d_in[3];
    const float* cK = (const float*)d_in[4];
    const float* cV = (const float*)d_in[5];
    float* out = (float*)d_out;

    float* qkv;
    bf16 *Xhi, *Xlo, *Wthi, *Wtlo, *Qhi, *Qlo, *Khi, *Klo;
    fp16 *Xh, *Wthv, *Vth;
    cudaGetSymbolAddress((void**)&qkv, g_qkv);
    cudaGetSymbolAddress((void**)&Xhi, g_Xhi);
    cudaGetSymbolAddress((void**)&Xlo, g_Xlo);
    cudaGetSymbolAddress((void**)&Xh, g_Xh);
    cudaGetSymbolAddress((void**)&Wthi, g_Wthi);
    cudaGetSymbolAddress((void**)&Wtlo, g_Wtlo);
    cudaGetSymbolAddress((void**)&Wthv, g_Wthv);
    cudaGetSymbolAddress((void**)&Qhi, g_Qhi);
    cudaGetSymbolAddress((void**)&Qlo, g_Qlo);
    cudaGetSymbolAddress((void**)&Khi, g_Khi);
    cudaGetSymbolAddress((void**)&Klo, g_Klo);
    cudaGetSymbolAddress((void**)&Vth, g_Vth);

    float* q = qkv;
    float* k = qkv + (size_t)MN;
    float* v = qkv + 2ull * MN;

    const int SM3 = 3 * (2 * 128 + 2 * 256) * 80;   // 184320
    const int SMH = 3 * (128 + 256) * 80;           // 92160
    cudaFuncSetAttribute(gemm3<256, 64>, cudaFuncAttributeMaxDynamicSharedMemorySize, SM3);
    cudaFuncSetAttribute(gemmh<256, 64>, cudaFuncAttributeMaxDynamicSharedMemorySize, SMH);
    cudaFuncSetAttribute(attn_fused, cudaFuncAttributeMaxDynamicSharedMemorySize, FA_SMEM);

    // 1) RMSNorm X -> bf16 hi/lo + fp16
    rmsnorm_split_x<<<MM, 256>>>(X, Xhi, Xlo, Xh);

    // 2) W transpose: Wq,Wk bf16 split; Wv fp16
    dim3 wgrid(NN / 32, NN / 32);
    wsplit_kernel<<<wgrid, 256>>>(Wq, Wthi + 0ull * NN * NN, Wtlo + 0ull * NN * NN);
    wsplit_kernel<<<wgrid, 256>>>(Wk, Wthi + 1ull * NN * NN, Wtlo + 1ull * NN * NN);
    wconv_kernel<<<wgrid, 256>>>(Wv, Wthv);

    // 3) q,k = Xn @ W (bf16x3, batch 2); v = Xn @ Wv (fp16x1)
    gemm3<256, 64><<<dim3(NN / 256, MM / 128, 2), 256, SM3>>>(
        Xhi, Xlo, Wthi, Wtlo, qkv, NN, NN, NN, NN,
        0LL, (long long)NN * NN, (long long)MN);
    gemmh<256, 64><<<dim3(NN / 256, MM / 128), 256, SMH>>>(
        Xh, Wthv, v, NN, NN, NN, NN);

    // 4) qk-norm: q -> Qhi/Qlo; k -> Khi/Klo appended region
    qknorm_split_kernel<<<(2 * MM * HH * 32) / 256, 256>>>(q, k, Qhi, Qlo, Khi, Klo);

    // 5) KV cache conversions (cache-only K bf16; full V^T fp16)
    build_khl<<<(int)((size_t)HH * PP * DD / 1024), 256>>>(cK, Khi, Klo);
    build_vt<<<dim3(KVLEN / 32, DD / 32, HH), 256>>>(cV, v, Vth);

    // 6) fused flash attention -> d_out
    attn_fused<<<dim3(MM / 128, HH), 256, FA_SMEM>>>(
        Qhi, Qlo, Khi, Klo, Vth, out);
}

// round 13
// speedup vs baseline: 1.4758x; 1.1237x over previous
#include <cuda_runtime.h>
#include <cuda_bf16.h>
#include <cuda_fp16.h>
#include <math.h>
#include <stdint.h>

typedef __nv_bfloat16 bf16;
typedef __half fp16;

// Problem constants
#define MM 1024
#define NN 4096
#define DD 128
#define HH 32
#define PP 4096
#define KVLEN 5120   // PP + MM
#define MN (MM * NN)

// ---------------------------------------------------------------------------
// Scratch (allocation-free rule: __device__ globals)
// ---------------------------------------------------------------------------
__device__ float g_qkv[3ull * MN];                   // q | k | v (fp32 gemm out)
__device__ fp16 g_Xh[MN];                            // rms-normed X, fp16
__device__ fp16 g_Wqkh[2ull * NN * NN];              // Wq,Wk transposed, fp16 hi
__device__ fp16 g_Wqkl[2ull * NN * NN];              // Wq,Wk transposed, fp16 lo
__device__ fp16 g_Wthv[(size_t)NN * NN];             // Wv transposed fp16
__device__ bf16 g_Qhi[MN];
__device__ bf16 g_Qlo[MN];
__device__ bf16 g_Khi[(size_t)HH * KVLEN * DD];      // [h][kv][d]
__device__ bf16 g_Klo[(size_t)HH * KVLEN * DD];
__device__ fp16 g_Vth[(size_t)HH * DD * KVLEN];      // [h][d][kv] fp16

// ---------------------------------------------------------------------------
// Helpers
// ---------------------------------------------------------------------------
__device__ __forceinline__ uint32_t smem_u32(const void* p) {
    uint32_t a;
    asm("{ .reg .u64 t; cvta.to.shared.u64 t, %1; cvt.u32.u64 %0, t; }" : "=r"(a) : "l"(p));
    return a;
}
__device__ __forceinline__ void ldsm_x4(uint32_t* r, uint32_t addr) {
    asm volatile("ldmatrix.sync.aligned.m8n8.x4.shared.b16 {%0,%1,%2,%3}, [%4];"
                 : "=r"(r[0]), "=r"(r[1]), "=r"(r[2]), "=r"(r[3]) : "r"(addr));
}
__device__ __forceinline__ void ldsm_x2(uint32_t* r, uint32_t addr) {
    asm volatile("ldmatrix.sync.aligned.m8n8.x2.shared.b16 {%0,%1}, [%2];"
                 : "=r"(r[0]), "=r"(r[1]) : "r"(addr));
}
__device__ __forceinline__ void cp16(uint32_t saddr, const void* gaddr) {
    asm volatile("cp.async.cg.shared.global [%0], [%1], 16;"
                 :: "r"(saddr), "l"(gaddr) : "memory");
}
#define CP_COMMIT() asm volatile("cp.async.commit_group;" ::: "memory")
#define CP_WAIT1() asm volatile("cp.async.wait_group 1;" ::: "memory")
#define CP_WAIT0() asm volatile("cp.async.wait_group 0;" ::: "memory")

// bf16 inputs, fp32 acc
#define MMA_BF(d, a, b)                                                \
    asm volatile(                                                      \
        "mma.sync.aligned.m16n8k16.row.col.f32.bf16.bf16.f32 "         \
        "{%0,%1,%2,%3}, {%4,%5,%6,%7}, {%8,%9}, {%0,%1,%2,%3};"        \
        : "+f"((d)[0]), "+f"((d)[1]), "+f"((d)[2]), "+f"((d)[3])       \
        : "r"((a)[0]), "r"((a)[1]), "r"((a)[2]), "r"((a)[3]),          \
          "r"((b)[0]), "r"((b)[1]))
// fp16 inputs, fp32 acc
#define MMA_FP(d, a, b)                                                \
    asm volatile(                                                      \
        "mma.sync.aligned.m16n8k16.row.col.f32.f16.f16.f32 "           \
        "{%0,%1,%2,%3}, {%4,%5,%6,%7}, {%8,%9}, {%0,%1,%2,%3};"        \
        : "+f"((d)[0]), "+f"((d)[1]), "+f"((d)[2]), "+f"((d)[3])       \
        : "r"((a)[0]), "r"((a)[1]), "r"((a)[2]), "r"((a)[3]),          \
          "r"((b)[0]), "r"((b)[1]))

__device__ __forceinline__ void split2(float x, bf16& h, bf16& l) {
    h = __float2bfloat16(x);
    l = __float2bfloat16(x - __bfloat162float(h));
}
__device__ __forceinline__ void split2h(float x, fp16& h, fp16& l) {
    h = __float2half_rn(x);
    l = __float2half_rn(x - __half2float(h));
}
__device__ __forceinline__ uint32_t packh2(float a, float b) {
    __half2 t = __floats2half2_rn(a, b);
    return *(uint32_t*)&t;
}

// ---------------------------------------------------------------------------
// RMSNorm over rows of X [1024, 4096] -> fp16
// ---------------------------------------------------------------------------
__global__ __launch_bounds__(256) void rmsnorm_h_x(const float* __restrict__ X,
                                                   fp16* __restrict__ out) {
    int row = blockIdx.x;
    const float4* x4 = (const float4*)(X + (size_t)row * NN);
    float4 v[4];
    float ss = 0.f;
#pragma unroll
    for (int i = 0; i < 4; i++) {
        v[i] = x4[threadIdx.x + i * 256];
        ss += v[i].x * v[i].x + v[i].y * v[i].y + v[i].z * v[i].z + v[i].w * v[i].w;
    }
#pragma unroll
    for (int o = 16; o; o >>= 1) ss += __shfl_xor_sync(0xffffffffu, ss, o);
    __shared__ float wsum[8];
    int warp = threadIdx.x >> 5, lane = threadIdx.x & 31;
    if (lane == 0) wsum[warp] = ss;
    __syncthreads();
    float tot = 0.f;
#pragma unroll
    for (int w = 0; w < 8; w++) tot += wsum[w];
    float s = rsqrtf(tot * (1.0f / (float)NN));
#pragma unroll
    for (int i = 0; i < 4; i++) {
        size_t off = (size_t)row * NN + (threadIdx.x + i * 256) * 4;
        *(__half2*)(out + off)     = __floats2half2_rn(v[i].x * s, v[i].y * s);
        *(__half2*)(out + off + 2) = __floats2half2_rn(v[i].z * s, v[i].w * s);
    }
}

// ---------------------------------------------------------------------------
// Transpose + fp16 hi/lo split: W [K, N] fp32 -> Wh/Wl fp16 [N, K]
// ---------------------------------------------------------------------------
__global__ __launch_bounds__(256) void wsplith_kernel(const float* __restrict__ W,
                                                      fp16* __restrict__ hi,
                                                      fp16* __restrict__ lo) {
    __shared__ float t[32][33];
    int tx = threadIdx.x & 31, ty = threadIdx.x >> 5;
    int n0 = blockIdx.x * 32, k0 = blockIdx.y * 32;
#pragma unroll
    for (int i = 0; i < 4; i++)
        t[ty + i * 8][tx] = W[(size_t)(k0 + ty + i * 8) * NN + n0 + tx];
    __syncthreads();
#pragma unroll
    for (int i = 0; i < 4; i++) {
        float v = t[tx][ty + i * 8];
        fp16 h, l;
        split2h(v, h, l);
        size_t off = (size_t)(n0 + ty + i * 8) * NN + k0 + tx;
        hi[off] = h;
        lo[off] = l;
    }
}

// ---------------------------------------------------------------------------
// Transpose + convert W -> fp16 [N, K] (for Wv)
// ---------------------------------------------------------------------------
__global__ __launch_bounds__(256) void wconv_kernel(const float* __restrict__ W,
                                                    fp16* __restrict__ out) {
    __shared__ float t[32][33];
    int tx = threadIdx.x & 31, ty = threadIdx.x >> 5;
    int n0 = blockIdx.x * 32, k0 = blockIdx.y * 32;
#pragma unroll
    for (int i = 0; i < 4; i++)
        t[ty + i * 8][tx] = W[(size_t)(k0 + ty + i * 8) * NN + n0 + tx];
    __syncthreads();
#pragma unroll
    for (int i = 0; i < 4; i++) {
        size_t off = (size_t)(n0 + ty + i * 8) * NN + k0 + tx;
        out[off] = __float2half_rn(t[tx][ty + i * 8]);
    }
}

// ---------------------------------------------------------------------------
// Per-head RMSNorm over D=128 (reads fp32 q,k; writes bf16 hi/lo).
// q rows -> Qhi/Qlo; k rows -> KV cache appended region Khi/Klo[h][PP+m][d].
// ---------------------------------------------------------------------------
__global__ __launch_bounds__(256) void qknorm_split_kernel(const float* __restrict__ q,
                                                           const float* __restrict__ k,
                                                           bf16* __restrict__ Qh,
                                                           bf16* __restrict__ Ql,
                                                           bf16* __restrict__ Kh,
                                                           bf16* __restrict__ Kl) {
    int gw = (int)((blockIdx.x * blockDim.x + threadIdx.x) >> 5);
    int lane = threadIdx.x & 31;
    bool isq = (gw < MM * HH);
    int row = isq ? gw : gw - MM * HH;
    const float* src = isq ? q : k;
    float4 a = ((const float4*)(src + (size_t)row * DD))[lane];
    float ss = a.x * a.x + a.y * a.y + a.z * a.z + a.w * a.w;
#pragma unroll
    for (int o = 16; o; o >>= 1) ss += __shfl_xor_sync(0xffffffffu, ss, o);
    float s = rsqrtf(ss * (1.0f / (float)DD));
    a.x *= s; a.y *= s; a.z *= s; a.w *= s;
    bf16 h0, h1, h2, h3, l0, l1, l2, l3;
    split2(a.x, h0, l0); split2(a.y, h1, l1);
    split2(a.z, h2, l2); split2(a.w, h3, l3);
    size_t off;
    bf16 *dh, *dl;
    if (isq) {
        off = (size_t)row * DD + lane * 4;
        dh = Qh; dl = Ql;
    } else {
        int m = row / HH, h = row % HH;
        off = ((size_t)h * KVLEN + PP + m) * DD + lane * 4;
        dh = Kh; dl = Kl;
    }
    *(__nv_bfloat162*)(dh + off)     = __nv_bfloat162(h0, h1);
    *(__nv_bfloat162*)(dh + off + 2) = __nv_bfloat162(h2, h3);
    *(__nv_bfloat162*)(dl + off)     = __nv_bfloat162(l0, l1);
    *(__nv_bfloat162*)(dl + off + 2) = __nv_bfloat162(l2, l3);
}

// ---------------------------------------------------------------------------
// Build K cache hi/lo: CACHE portion only
// ---------------------------------------------------------------------------
__global__ __launch_bounds__(256) void build_khl(const float* __restrict__ cacheK,
                                                 bf16* __restrict__ Kh,
                                                 bf16* __restrict__ Kl) {
    size_t e = ((size_t)blockIdx.x * 256 + threadIdx.x) * 4;
    int h = (int)(e / ((size_t)PP * DD));
    int rem = (int)(e % ((size_t)PP * DD));
    float4 v = *(const float4*)(cacheK + e);
    bf16 h0, h1, h2, h3, l0, l1, l2, l3;
    split2(v.x, h0, l0); split2(v.y, h1, l1);
    split2(v.z, h2, l2); split2(v.w, h3, l3);
    size_t o = (size_t)h * KVLEN * DD + rem;
    *(__nv_bfloat162*)(Kh + o)     = __nv_bfloat162(h0, h1);
    *(__nv_bfloat162*)(Kh + o + 2) = __nv_bfloat162(h2, h3);
    *(__nv_bfloat162*)(Kl + o)     = __nv_bfloat162(l0, l1);
    *(__nv_bfloat162*)(Kl + o + 2) = __nv_bfloat162(l2, l3);
}

// ---------------------------------------------------------------------------
// Build V^T fp16: [h][d][kv]
// ---------------------------------------------------------------------------
__global__ __launch_bounds__(256) void build_vt(const float* __restrict__ cacheV,
                                                const float* __restrict__ vproj,
                                                fp16* __restrict__ Vh) {
    __shared__ float t[32][33];
    int tx = threadIdx.x & 31, ty = threadIdx.x >> 5;
    int kv0 = blockIdx.x * 32, d0 = blockIdx.y * 32, h = blockIdx.z;
#pragma unroll
    for (int i = 0; i < 4; i++) {
        int r = kv0 + ty + i * 8;
        int c = d0 + tx;
        float v = (r < PP)
            ? cacheV[((size_t)h * PP + r) * DD + c]
            : vproj[(size_t)(r - PP) * NN + h * DD + c];
        t[ty + i * 8][tx] = v;
    }
    __syncthreads();
#pragma unroll
    for (int i = 0; i < 4; i++) {
        int d = d0 + ty + i * 8;
        size_t off = ((size_t)h * DD + d) * KVLEN + kv0 + tx;
        Vh[off] = __float2half_rn(t[tx][ty + i * 8]);
    }
}

// ---------------------------------------------------------------------------
// 2-term fp16 GEMM: C = A @ (Bh + Bl)^T,  A single fp16, B split fp16 hi/lo.
// 3-slot / 2-in-flight cp.async pipeline, one __syncthreads per K-chunk.
// Used for q,k projections (batch via blockIdx.z on B/C; A shared).
// ---------------------------------------------------------------------------
template <int BN, int WN>
__global__ __launch_bounds__(256, 1) void gemm2h(
    const fp16* __restrict__ A, const fp16* __restrict__ Bh,
    const fp16* __restrict__ Bl, float* __restrict__ C,
    int K, int lda, int ldb, int ldc, long long sB, long long sC) {
    constexpr int BM = 128;
    constexpr int NFR = WN / 8;
    constexpr int PADB = 80;
    constexpr int STG = (BM + 2 * BN) * PADB;
    extern __shared__ char smraw[];

    const int tid = threadIdx.x;
    const int lane = tid & 31, wid = tid >> 5;
    const int wr = wid >> 2, wc = wid & 3;
    const int m0 = blockIdx.y * BM, n0 = blockIdx.x * BN;
    Bh += (long long)blockIdx.z * sB;
    Bl += (long long)blockIdx.z * sB;
    C += (long long)blockIdx.z * sC;

    float acc[4][NFR][4];
#pragma unroll
    for (int f = 0; f < 4; f++)
#pragma unroll
        for (int j = 0; j < NFR; j++)
#pragma unroll
            for (int x = 0; x < 4; x++) acc[f][j][x] = 0.f;

    const uint32_t sbase = smem_u32(smraw);
    const uint32_t aoff = (uint32_t)((wr * 64 + (lane & 15)) * PADB + (lane >> 4) * 16);
    const uint32_t boff = (uint32_t)((wc * WN + (lane & 7)) * PADB + ((lane >> 3) & 1) * 16);

    auto issue = [&](int slot, int k0) {
        uint32_t ba = sbase + slot * STG;
        const fp16* pA = A + (size_t)m0 * lda + k0;
#pragma unroll
        for (int i = tid; i < BM * 4; i += 256) {
            int r = i >> 2, cb = (i & 3) * 16;
            cp16(ba + r * PADB + cb, (const char*)(pA + (size_t)r * lda) + cb);
        }
        uint32_t bb = ba + BM * PADB;
        const fp16* pBh = Bh + (size_t)n0 * ldb + k0;
        const fp16* pBl = Bl + (size_t)n0 * ldb + k0;
#pragma unroll
        for (int i = tid; i < BN * 4; i += 256) {
            int r = i >> 2, cb = (i & 3) * 16;
            cp16(bb + r * PADB + cb, (const char*)(pBh + (size_t)r * ldb) + cb);
            cp16(bb + BN * PADB + r * PADB + cb, (const char*)(pBl + (size_t)r * ldb) + cb);
        }
        CP_COMMIT();
    };

    const int nch = K >> 5;
    issue(0, 0);
    if (nch > 1) issue(1, 32);

    for (int kc = 0; kc < nch; kc++) {
        if (kc + 1 < nch) { CP_WAIT1(); } else { CP_WAIT0(); }
        __syncthreads();
        if (kc + 2 < nch) issue((kc + 2) % 3, (kc + 2) << 5);

        const uint32_t aB = sbase + (kc % 3) * STG;
        const uint32_t bH = aB + BM * PADB;
        const uint32_t bL = bH + BN * PADB;
#pragma unroll
        for (int ks = 0; ks < 2; ks++) {
            uint32_t af[4][4];
#pragma unroll
            for (int f = 0; f < 4; f++)
                ldsm_x4(af[f], aB + aoff + f * 16 * PADB + ks * 32);
#pragma unroll
            for (int j = 0; j < NFR; j++) {
                uint32_t off = boff + j * 8 * PADB + ks * 32;
                uint32_t bh[2], bl[2];
                ldsm_x2(bh, bH + off);
                ldsm_x2(bl, bL + off);
#pragma unroll
                for (int f = 0; f < 4; f++) MMA_FP(acc[f][j], af[f], bh);
#pragma unroll
                for (int f = 0; f < 4; f++) MMA_FP(acc[f][j], af[f], bl);
            }
        }
    }
    __syncthreads();

#pragma unroll
    for (int f = 0; f < 4; f++) {
        int row = m0 + wr * 64 + f * 16 + (lane >> 2);
#pragma unroll
        for (int j = 0; j < NFR; j++) {
            int col = n0 + wc * WN + j * 8 + (lane & 3) * 2;
            *(float2*)(C + (size_t)row * ldc + col) = make_float2(acc[f][j][0], acc[f][j][1]);
            *(float2*)(C + (size_t)(row + 8) * ldc + col) = make_float2(acc[f][j][2], acc[f][j][3]);
        }
    }
}

// ---------------------------------------------------------------------------
// fp16 single-term GEMM — used for v projection
// ---------------------------------------------------------------------------
template <int BN, int WN>
__global__ __launch_bounds__(256, 1) void gemmh(
    const fp16* __restrict__ A, const fp16* __restrict__ B,
    float* __restrict__ C, int K, int lda, int ldb, int ldc) {
    constexpr int BM = 128;
    constexpr int NFR = WN / 8;
    constexpr int PADB = 80;
    constexpr int STG = (BM + BN) * PADB;
    extern __shared__ char smraw[];

    const int tid = threadIdx.x;
    const int lane = tid & 31, wid = tid >> 5;
    const int wr = wid >> 2, wc = wid & 3;
    const int m0 = blockIdx.y * BM, n0 = blockIdx.x * BN;

    float acc[4][NFR][4];
#pragma unroll
    for (int f = 0; f < 4; f++)
#pragma unroll
        for (int j = 0; j < NFR; j++)
#pragma unroll
            for (int x = 0; x < 4; x++) acc[f][j][x] = 0.f;

    const uint32_t sbase = smem_u32(smraw);
    const uint32_t aoff = (uint32_t)((wr * 64 + (lane & 15)) * PADB + (lane >> 4) * 16);
    const uint32_t boff = (uint32_t)((wc * WN + (lane & 7)) * PADB + ((lane >> 3) & 1) * 16);

    auto issue = [&](int slot, int k0) {
        uint32_t ba = sbase + slot * STG;
        const fp16* pA = A + (size_t)m0 * lda + k0;
#pragma unroll
        for (int i = tid; i < BM * 4; i += 256) {
            int r = i >> 2, cb = (i & 3) * 16;
            cp16(ba + r * PADB + cb, (const char*)(pA + (size_t)r * lda) + cb);
        }
        uint32_t bb = ba + BM * PADB;
        const fp16* pB = B + (size_t)n0 * ldb + k0;
#pragma unroll
        for (int i = tid; i < BN * 4; i += 256) {
            int r = i >> 2, cb = (i & 3) * 16;
            cp16(bb + r * PADB + cb, (const char*)(pB + (size_t)r * ldb) + cb);
        }
        CP_COMMIT();
    };

    const int nch = K >> 5;
    issue(0, 0);
    if (nch > 1) issue(1, 32);

    for (int kc = 0; kc < nch; kc++) {
        if (kc + 1 < nch) { CP_WAIT1(); } else { CP_WAIT0(); }
        __syncthreads();
        if (kc + 2 < nch) issue((kc + 2) % 3, (kc + 2) << 5);

        const uint32_t aB = sbase + (kc % 3) * STG;
        const uint32_t bB = aB + BM * PADB;
#pragma unroll
        for (int ks = 0; ks < 2; ks++) {
            uint32_t af[4][4];
#pragma unroll
            for (int f = 0; f < 4; f++)
                ldsm_x4(af[f], aB + aoff + f * 16 * PADB + ks * 32);
#pragma unroll
            for (int j = 0; j < NFR; j++) {
                uint32_t bf[2];
                ldsm_x2(bf, bB + boff + j * 8 * PADB + ks * 32);
#pragma unroll
                for (int f = 0; f < 4; f++) MMA_FP(acc[f][j], af[f], bf);
            }
        }
    }
    __syncthreads();

#pragma unroll
    for (int f = 0; f < 4; f++) {
        int row = m0 + wr * 64 + f * 16 + (lane >> 2);
#pragma unroll
        for (int j = 0; j < NFR; j++) {
            int col = n0 + wc * WN + j * 8 + (lane & 3) * 2;
            *(float2*)(C + (size_t)row * ldc + col) = make_float2(acc[f][j][0], acc[f][j][1]);
            *(float2*)(C + (size_t)(row + 8) * ldc + col) = make_float2(acc[f][j][2], acc[f][j][3]);
        }
    }
}

// ---------------------------------------------------------------------------
// Fused flash attention (R12-proven): S = QK^T bf16x3, PV single fp16.
// ---------------------------------------------------------------------------
#define FA_KPAD 272
#define FA_VPAD 144
#define FA_QB (128 * FA_KPAD)
#define FA_KT (64 * FA_KPAD)
#define FA_VT (128 * FA_VPAD)
#define FA_STG (2 * FA_KT + FA_VT)
#define FA_SMEM (2 * FA_QB + 2 * FA_STG)   // 176128

__global__ __launch_bounds__(256, 1) void attn_fused(
    const bf16* __restrict__ Qh_, const bf16* __restrict__ Ql_,
    const bf16* __restrict__ Kh_, const bf16* __restrict__ Kl_,
    const fp16* __restrict__ Vh_, float* __restrict__ out) {
    extern __shared__ char sm[];
    const int tid = threadIdx.x, lane = tid & 31, wid = tid >> 5;
    const int m0 = blockIdx.x * 128, h = blockIdx.y;
    const uint32_t sb = smem_u32(sm);

    const bf16* Khh = Kh_ + (size_t)h * KVLEN * DD;
    const bf16* Klh = Kl_ + (size_t)h * KVLEN * DD;
    const fp16* Vhh = Vh_ + (size_t)h * DD * KVLEN;

#pragma unroll
    for (int i = tid; i < 128 * 16; i += 256) {
        int r = i >> 4, c = i & 15;
        size_t go = (size_t)(m0 + r) * NN + h * DD + c * 8;
        cp16(sb + r * FA_KPAD + c * 16, Qh_ + go);
        cp16(sb + FA_QB + r * FA_KPAD + c * 16, Ql_ + go);
    }

    auto issue = [&](int s, int kv0) {
        uint32_t kb = sb + 2 * FA_QB + s * FA_STG;
#pragma unroll
        for (int i = tid; i < 1024; i += 256) {
            int r = i >> 4, c = i & 15;
            size_t go = (size_t)(kv0 + r) * DD + c * 8;
            cp16(kb + r * FA_KPAD + c * 16, Khh + go);
            cp16(kb + FA_KT + r * FA_KPAD + c * 16, Klh + go);
        }
        uint32_t vb = kb + 2 * FA_KT;
#pragma unroll
        for (int i = tid; i < 1024; i += 256) {
            int r = i >> 3, c = i & 7;
            cp16(vb + r * FA_VPAD + c * 16, Vhh + (size_t)r * KVLEN + kv0 + c * 8);
        }
        CP_COMMIT();
    };

    float oacc[16][4];
#pragma unroll
    for (int j = 0; j < 16; j++)
#pragma unroll
        for (int x = 0; x < 4; x++) oacc[j][x] = 0.f;
    float mrow0 = -INFINITY, mrow8 = -INFINITY;
    float lrow0 = 0.f, lrow8 = 0.f;

    const uint32_t qoff = (uint32_t)((wid * 16 + (lane & 15)) * FA_KPAD + (lane >> 4) * 16);
    const uint32_t koff = (uint32_t)((lane & 7) * FA_KPAD + ((lane >> 3) & 1) * 16);
    const uint32_t voff = (uint32_t)((lane & 7) * FA_VPAD + ((lane >> 3) & 1) * 16);

    issue(0, 0);

    for (int ch = 0; ch < KVLEN / 64; ch++) {
        const int s = ch & 1;
        if (ch + 1 < KVLEN / 64) {
            issue(s ^ 1, (ch + 1) * 64);
            CP_WAIT1();
        } else {
            CP_WAIT0();
        }
        __syncthreads();

        const uint32_t bKh = sb + 2 * FA_QB + s * FA_STG;
        const uint32_t bKl = bKh + FA_KT;
        const uint32_t bV = bKh + 2 * FA_KT;

        float sacc[8][4];
#pragma unroll
        for (int j = 0; j < 8; j++)
#pragma unroll
            for (int x = 0; x < 4; x++) sacc[j][x] = 0.f;
#pragma unroll
        for (int ks = 0; ks < 8; ks++) {
            uint32_t qh[4], ql[4];
            ldsm_x4(qh, sb + qoff + ks * 32);
            ldsm_x4(ql, sb + FA_QB + qoff + ks * 32);
            uint32_t kh[8][2], kl[8][2];
#pragma unroll
            for (int j = 0; j < 8; j++) {
                uint32_t off = koff + j * 8 * FA_KPAD + ks * 32;
                ldsm_x2(kh[j], bKh + off);
                ldsm_x2(kl[j], bKl + off);
            }
#pragma unroll
            for (int j = 0; j < 8; j++) MMA_BF(sacc[j], qh, kh[j]);
#pragma unroll
            for (int j = 0; j < 8; j++) MMA_BF(sacc[j], qh, kl[j]);
#pragma unroll
            for (int j = 0; j < 8; j++) MMA_BF(sacc[j], ql, kh[j]);
        }

        float mx0 = -INFINITY, mx8 = -INFINITY;
#pragma unroll
        for (int j = 0; j < 8; j++) {
            mx0 = fmaxf(mx0, fmaxf(sacc[j][0], sacc[j][1]));
            mx8 = fmaxf(mx8, fmaxf(sacc[j][2], sacc[j][3]));
        }
        mx0 = fmaxf(mx0, __shfl_xor_sync(0xffffffffu, mx0, 1));
        mx0 = fmaxf(mx0, __shfl_xor_sync(0xffffffffu, mx0, 2));
        mx8 = fmaxf(mx8, __shfl_xor_sync(0xffffffffu, mx8, 1));
        mx8 = fmaxf(mx8, __shfl_xor_sync(0xffffffffu, mx8, 2));
        float mn0 = fmaxf(mrow0, mx0), mn8 = fmaxf(mrow8, mx8);
        float sc0 = __expf(mrow0 - mn0), sc8 = __expf(mrow8 - mn8);
        mrow0 = mn0; mrow8 = mn8;
        float ps0 = 0.f, ps8 = 0.f;
#pragma unroll
        for (int j = 0; j < 8; j++) {
            sacc[j][0] = __expf(sacc[j][0] - mn0);
            sacc[j][1] = __expf(sacc[j][1] - mn0);
            sacc[j][2] = __expf(sacc[j][2] - mn8);
            sacc[j][3] = __expf(sacc[j][3] - mn8);
            ps0 += sacc[j][0] + sacc[j][1];
            ps8 += sacc[j][2] + sacc[j][3];
        }
        lrow0 = lrow0 * sc0 + ps0;
        lrow8 = lrow8 * sc8 + ps8;
#pragma unroll
        for (int j = 0; j < 16; j++) {
            oacc[j][0] *= sc0; oacc[j][1] *= sc0;
            oacc[j][2] *= sc8; oacc[j][3] *= sc8;
        }

        uint32_t pf[4][4];
#pragma unroll
        for (int kk = 0; kk < 4; kk++) {
            pf[kk][0] = packh2(sacc[2 * kk][0], sacc[2 * kk][1]);
            pf[kk][1] = packh2(sacc[2 * kk][2], sacc[2 * kk][3]);
            pf[kk][2] = packh2(sacc[2 * kk + 1][0], sacc[2 * kk + 1][1]);
            pf[kk][3] = packh2(sacc[2 * kk + 1][2], sacc[2 * kk + 1][3]);
        }

#pragma unroll
        for (int kk = 0; kk < 4; kk++) {
#pragma unroll
            for (int jh = 0; jh < 2; jh++) {
                uint32_t vf[8][2];
#pragma unroll
                for (int j = 0; j < 8; j++)
                    ldsm_x2(vf[j], bV + voff + (jh * 8 + j) * 8 * FA_VPAD + kk * 32);
#pragma unroll
                for (int j = 0; j < 8; j++) MMA_FP(oacc[jh * 8 + j], pf[kk], vf[j]);
            }
        }
        __syncthreads();
    }

    lrow0 += __shfl_xor_sync(0xffffffffu, lrow0, 1);
    lrow0 += __shfl_xor_sync(0xffffffffu, lrow0, 2);
    lrow8 += __shfl_xor_sync(0xffffffffu, lrow8, 1);
    lrow8 += __shfl_xor_sync(0xffffffffu, lrow8, 2);
    float inv0 = 1.0f / lrow0, inv8 = 1.0f / lrow8;
    int r0 = m0 + wid * 16 + (lane >> 2);
#pragma unroll
    for (int j = 0; j < 16; j++) {
        int col = h * DD + j * 8 + (lane & 3) * 2;
        *(float2*)(out + (size_t)r0 * NN + col) =
            make_float2(oacc[j][0] * inv0, oacc[j][1] * inv0);
        *(float2*)(out + (size_t)(r0 + 8) * NN + col) =
            make_float2(oacc[j][2] * inv8, oacc[j][3] * inv8);
    }
}

// ---------------------------------------------------------------------------
extern "C" void kernel_launch(void* const* d_in, const int* in_sizes, int n_in,
                              void* d_out, int out_size) {
    const float* X  = (const float*)d_in[0];
    const float* Wq = (const float*)d_in[1];
    const float* Wk = (const float*)d_in[2];
    const float* Wv = (const float*)d_in[3];
    const float* cK = (const float*)d_in[4];
    const float* cV = (const float*)d_in[5];
    float* out = (float*)d_out;

    float* qkv;
    bf16 *Qhi, *Qlo, *Khi, *Klo;
    fp16 *Xh, *Wqkh, *Wqkl, *Wthv, *Vth;
    cudaGetSymbolAddress((void**)&qkv, g_qkv);
    cudaGetSymbolAddress((void**)&Xh, g_Xh);
    cudaGetSymbolAddress((void**)&Wqkh, g_Wqkh);
    cudaGetSymbolAddress((void**)&Wqkl, g_Wqkl);
    cudaGetSymbolAddress((void**)&Wthv, g_Wthv);
    cudaGetSymbolAddress((void**)&Qhi, g_Qhi);
    cudaGetSymbolAddress((void**)&Qlo, g_Qlo);
    cudaGetSymbolAddress((void**)&Khi, g_Khi);
    cudaGetSymbolAddress((void**)&Klo, g_Klo);
    cudaGetSymbolAddress((void**)&Vth, g_Vth);

    float* q = qkv;
    float* k = qkv + (size_t)MN;
    float* v = qkv + 2ull * MN;

    const int SM2 = 3 * (128 + 2 * 256) * 80;   // 153600
    const int SMH = 3 * (128 + 256) * 80;       // 92160
    cudaFuncSetAttribute(gemm2h<256, 64>, cudaFuncAttributeMaxDynamicSharedMemorySize, SM2);
    cudaFuncSetAttribute(gemmh<256, 64>, cudaFuncAttributeMaxDynamicSharedMemorySize, SMH);
    cudaFuncSetAttribute(attn_fused, cudaFuncAttributeMaxDynamicSharedMemorySize, FA_SMEM);

    // 1) RMSNorm X -> fp16
    rmsnorm_h_x<<<MM, 256>>>(X, Xh);

    // 2) W transpose: Wq,Wk fp16 hi/lo split; Wv fp16 single
    dim3 wgrid(NN / 32, NN / 32);
    wsplith_kernel<<<wgrid, 256>>>(Wq, Wqkh + 0ull * NN * NN, Wqkl + 0ull * NN * NN);
    wsplith_kernel<<<wgrid, 256>>>(Wk, Wqkh + 1ull * NN * NN, Wqkl + 1ull * NN * NN);
    wconv_kernel<<<wgrid, 256>>>(Wv, Wthv);

    // 3) q,k = Xh @ (Wh+Wl) (fp16x2, batch 2); v = Xh @ Wv (fp16x1)
    gemm2h<256, 64><<<dim3(NN / 256, MM / 128, 2), 256, SM2>>>(
        Xh, Wqkh, Wqkl, qkv, NN, NN, NN, NN,
        (long long)NN * NN, (long long)MN);
    gemmh<256, 64><<<dim3(NN / 256, MM / 128), 256, SMH>>>(
        Xh, Wthv, v, NN, NN, NN, NN);

    // 4) qk-norm: q -> Qhi/Qlo; k -> Khi/Klo appended region
    qknorm_split_kernel<<<(2 * MM * HH * 32) / 256, 256>>>(q, k, Qhi, Qlo, Khi, Klo);

    // 5) KV cache conversions (cache-only K bf16; full V^T fp16)
    build_khl<<<(int)((size_t)HH * PP * DD / 1024), 256>>>(cK, Khi, Klo);
    build_vt<<<dim3(KVLEN / 32, DD / 32, HH), 256>>>(cV, v, Vth);

    // 6) fused flash attention -> d_out
    attn_fused<<<dim3(MM / 128, HH), 256, FA_SMEM>>>(
        Qhi, Qlo, Khi, Klo, Vth, out);
}